// round 1
// baseline (speedup 1.0000x reference)
#include <cuda_runtime.h>
#include <cuda_bf16.h>
#include <math.h>

#define B_  2
#define T_  2048
#define D_  1024
#define H_  16
#define DH_ 64
#define QKV_COLS 3072   // 3*D
#define BT_ (B_*T_)     // 4096

// Scratch (allocation-free rule: __device__ globals)
__device__ float g_qkv[(size_t)BT_ * QKV_COLS]; // 48 MB
__device__ float g_y[(size_t)BT_ * D_];         // 16 MB

// ---------------------------------------------------------------------------
// SGEMM (NT): C[m][n] = sum_k A[m][k] * W[n][k] + bias[n]
// BM=BN=128, BK=16, 256 threads, 8x8 micro-tile
// ---------------------------------------------------------------------------
__global__ __launch_bounds__(256, 2)
void sgemm_nt_kernel(const float* __restrict__ A, const float* __restrict__ W,
                     const float* __restrict__ bias, float* __restrict__ C,
                     int M, int N, int K) {
    const int BM = 128, BN = 128, BK = 16;
    __shared__ float As[BK][BM + 4];
    __shared__ float Bs[BK][BN + 4];

    int tid = threadIdx.x;
    int tx = tid & 15;        // 0..15
    int ty = tid >> 4;        // 0..15
    int m0 = blockIdx.y * BM;
    int n0 = blockIdx.x * BN;

    int loadRow = tid >> 2;         // 0..63
    int loadCol = (tid & 3) * 4;    // 0,4,8,12

    float acc[8][8];
#pragma unroll
    for (int i = 0; i < 8; i++)
#pragma unroll
        for (int j = 0; j < 8; j++) acc[i][j] = 0.f;

    for (int k0 = 0; k0 < K; k0 += BK) {
        // load A tile (128 x 16) -> As transposed
        {
            const float4 a0 = *(const float4*)(A + (size_t)(m0 + loadRow) * K + k0 + loadCol);
            const float4 a1 = *(const float4*)(A + (size_t)(m0 + loadRow + 64) * K + k0 + loadCol);
            As[loadCol + 0][loadRow] = a0.x;
            As[loadCol + 1][loadRow] = a0.y;
            As[loadCol + 2][loadRow] = a0.z;
            As[loadCol + 3][loadRow] = a0.w;
            As[loadCol + 0][loadRow + 64] = a1.x;
            As[loadCol + 1][loadRow + 64] = a1.y;
            As[loadCol + 2][loadRow + 64] = a1.z;
            As[loadCol + 3][loadRow + 64] = a1.w;
            const float4 b0 = *(const float4*)(W + (size_t)(n0 + loadRow) * K + k0 + loadCol);
            const float4 b1 = *(const float4*)(W + (size_t)(n0 + loadRow + 64) * K + k0 + loadCol);
            Bs[loadCol + 0][loadRow] = b0.x;
            Bs[loadCol + 1][loadRow] = b0.y;
            Bs[loadCol + 2][loadRow] = b0.z;
            Bs[loadCol + 3][loadRow] = b0.w;
            Bs[loadCol + 0][loadRow + 64] = b1.x;
            Bs[loadCol + 1][loadRow + 64] = b1.y;
            Bs[loadCol + 2][loadRow + 64] = b1.z;
            Bs[loadCol + 3][loadRow + 64] = b1.w;
        }
        __syncthreads();

#pragma unroll
        for (int kk = 0; kk < BK; kk++) {
            float ra[8], rb[8];
#pragma unroll
            for (int i = 0; i < 8; i++) ra[i] = As[kk][ty * 8 + i];
#pragma unroll
            for (int j = 0; j < 8; j++) rb[j] = Bs[kk][tx * 8 + j];
#pragma unroll
            for (int i = 0; i < 8; i++)
#pragma unroll
                for (int j = 0; j < 8; j++) acc[i][j] += ra[i] * rb[j];
        }
        __syncthreads();
    }

#pragma unroll
    for (int i = 0; i < 8; i++) {
        int m = m0 + ty * 8 + i;
#pragma unroll
        for (int j = 0; j < 8; j++) {
            int n = n0 + tx * 8 + j;
            C[(size_t)m * N + n] = acc[i][j] + bias[n];
        }
    }
}

// ---------------------------------------------------------------------------
// RoPE-variant applied in-place to q and k slices of g_qkv.
// out[2i]   = x[2i]*cos - x[2i+1]*(1-cos)
// out[2i+1] = x[2i+1]*sin + x[2i]*(1-sin)
// ---------------------------------------------------------------------------
__global__ void rope_kernel(float* __restrict__ qkv) {
    int idx = blockIdx.x * blockDim.x + threadIdx.x;
    const int total = BT_ * H_ * (DH_ / 2);
    if (idx >= total) return;
    int i = idx & 31;          // pair index 0..31
    int h = (idx >> 5) & 15;   // head
    int bt = idx >> 9;         // 0..4095
    int t = bt & (T_ - 1);

    float freq = __powf(10000.f, (2.f * (float)i) / (float)DH_);
    float ang = (float)t / freq;
    float c, s;
    __sincosf(ang, &s, &c);

    float* base = qkv + (size_t)bt * QKV_COLS + h * (3 * DH_);
    // q
    float e = base[2 * i], o = base[2 * i + 1];
    base[2 * i]     = e * c - o * (1.f - c);
    base[2 * i + 1] = o * s + e * (1.f - s);
    // k
    e = base[DH_ + 2 * i];
    o = base[DH_ + 2 * i + 1];
    base[DH_ + 2 * i]     = e * c - o * (1.f - c);
    base[DH_ + 2 * i + 1] = o * s + e * (1.f - s);
}

// ---------------------------------------------------------------------------
// Flash attention (causal). One block = (b,h, 128-query tile).
// 128 threads, thread r owns query row m0+r: q[64], acc[64] in registers.
// KV tiles of 64 staged in shared; scores staged in padded shared.
// ---------------------------------------------------------------------------
#define MT 128
#define KT 64

__global__ __launch_bounds__(128, 1)
void attn_kernel(const float* __restrict__ qkv, float* __restrict__ y) {
    int mtile = blockIdx.x;          // 0..15
    int bh = blockIdx.y;             // 0..31
    int b = bh >> 4, h = bh & 15;
    int r = threadIdx.x;             // 0..127
    int m = mtile * MT + r;

    extern __shared__ float sm[];
    float* Ksh = sm;                   // KT*DH
    float* Vsh = sm + KT * DH_;        // KT*DH
    float* Ssh = sm + 2 * KT * DH_;    // MT*(KT+1)

    const float* qbase = qkv + (size_t)(b * T_ + m) * QKV_COLS + h * (3 * DH_);
    float q[DH_];
#pragma unroll
    for (int d = 0; d < DH_; d++) q[d] = qbase[d];

    float acc[DH_];
#pragma unroll
    for (int d = 0; d < DH_; d++) acc[d] = 0.f;
    float mi = -1e30f, li = 0.f;

    const int s_end = mtile * MT + MT;
    for (int s0 = 0; s0 < s_end; s0 += KT) {
        __syncthreads();
        // cooperative load of K and V tiles (coalesced 64-float rows)
        for (int i = r; i < KT * DH_; i += MT) {
            int j = i >> 6, d = i & 63;
            const float* kb = qkv + (size_t)(b * T_ + s0 + j) * QKV_COLS + h * (3 * DH_);
            Ksh[i] = kb[DH_ + d];
            Vsh[i] = kb[2 * DH_ + d];
        }
        __syncthreads();

        float mnew = mi;
        bool needMask = (s0 + KT - 1) > m;
        float* srow = Ssh + r * (KT + 1);
#pragma unroll 4
        for (int j = 0; j < KT; j++) {
            const float* krow = Ksh + j * DH_;
            float dot = 0.f;
#pragma unroll
            for (int d = 0; d < DH_; d++) dot += q[d] * krow[d];
            dot *= 0.125f;   // 1/sqrt(64)
            if (needMask && (s0 + j > m)) dot = -1e30f;
            srow[j] = dot;
            mnew = fmaxf(mnew, dot);
        }

        float alpha = __expf(mi - mnew);
        li *= alpha;
#pragma unroll
        for (int d = 0; d < DH_; d++) acc[d] *= alpha;

#pragma unroll 2
        for (int j = 0; j < KT; j++) {
            float p = __expf(srow[j] - mnew);
            li += p;
            const float* vrow = Vsh + j * DH_;
#pragma unroll
            for (int d = 0; d < DH_; d++) acc[d] += p * vrow[d];
        }
        mi = mnew;
    }

    float inv = 1.f / li;
    float* yb = y + (size_t)(b * T_ + m) * D_ + h * DH_;
#pragma unroll
    for (int d = 0; d < DH_; d++) yb[d] = acc[d] * inv;
}

// ---------------------------------------------------------------------------
// Launch
// ---------------------------------------------------------------------------
extern "C" void kernel_launch(void* const* d_in, const int* in_sizes, int n_in,
                              void* d_out, int out_size) {
    const float* x     = (const float*)d_in[0];
    const float* Wqkv  = (const float*)d_in[1];
    const float* bqkv  = (const float*)d_in[2];
    const float* Wproj = (const float*)d_in[3];
    const float* bproj = (const float*)d_in[4];
    float* out = (float*)d_out;

    float* qkv = nullptr;
    float* y = nullptr;
    cudaGetSymbolAddress((void**)&qkv, g_qkv);
    cudaGetSymbolAddress((void**)&y, g_y);

    // 1) QKV GEMM: (4096 x 1024) x (3072 x 1024)^T
    {
        dim3 grid(QKV_COLS / 128, BT_ / 128);
        sgemm_nt_kernel<<<grid, 256>>>(x, Wqkv, bqkv, qkv, BT_, QKV_COLS, D_);
    }

    // 2) RoPE on q,k
    {
        int total = BT_ * H_ * (DH_ / 2);
        rope_kernel<<<(total + 255) / 256, 256>>>(qkv);
    }

    // 3) Flash attention
    {
        int smem = (2 * KT * DH_ + MT * (KT + 1)) * (int)sizeof(float); // 66048 B
        cudaFuncSetAttribute(attn_kernel, cudaFuncAttributeMaxDynamicSharedMemorySize, smem);
        dim3 grid(T_ / MT, B_ * H_);
        attn_kernel<<<grid, MT, smem>>>(qkv, y);
    }

    // 4) Proj GEMM: (4096 x 1024) x (1024 x 1024)^T
    {
        dim3 grid(D_ / 128, BT_ / 128);
        sgemm_nt_kernel<<<grid, 256>>>(y, Wproj, bproj, out, BT_, D_, D_);
    }
}

// round 2
// speedup vs baseline: 3.8760x; 3.8760x over previous
#include <cuda_runtime.h>
#include <cuda_bf16.h>
#include <math.h>
#include <stdint.h>

#define B_  2
#define T_  2048
#define D_  1024
#define H_  16
#define DH_ 64
#define QKV_COLS 3072   // 3*D
#define BT_ (B_*T_)     // 4096

// Scratch (allocation-free rule: __device__ globals)
__device__ float g_qkv[(size_t)BT_ * QKV_COLS];   // 48 MB
__device__ float g_y[(size_t)BT_ * D_];           // 16 MB
__device__ float g_xr[(size_t)BT_ * D_];          // 16 MB (tf32-rounded x)
__device__ float g_wqkvr[(size_t)QKV_COLS * D_];  // 12 MB
__device__ float g_wprojr[(size_t)D_ * D_];       // 4 MB

// ---------------------------------------------------------------------------
// Helpers
// ---------------------------------------------------------------------------
__device__ __forceinline__ float tf32r(float x) {
    uint32_t u;
    asm("cvt.rna.tf32.f32 %0, %1;" : "=r"(u) : "f"(x));
    return __uint_as_float(u);
}

__device__ __forceinline__ void mma_tf32(float* c, const float* a, const float* b) {
    asm volatile(
        "mma.sync.aligned.m16n8k8.row.col.f32.tf32.tf32.f32 "
        "{%0,%1,%2,%3}, {%4,%5,%6,%7}, {%8,%9}, {%0,%1,%2,%3};"
        : "+f"(c[0]), "+f"(c[1]), "+f"(c[2]), "+f"(c[3])
        : "r"(__float_as_uint(a[0])), "r"(__float_as_uint(a[1])),
          "r"(__float_as_uint(a[2])), "r"(__float_as_uint(a[3])),
          "r"(__float_as_uint(b[0])), "r"(__float_as_uint(b[1])));
}

__device__ __forceinline__ void cpa16(void* smem, const void* g) {
    uint32_t s = (uint32_t)__cvta_generic_to_shared(smem);
    asm volatile("cp.async.cg.shared.global [%0], [%1], 16;" :: "r"(s), "l"(g));
}
#define CP_COMMIT() asm volatile("cp.async.commit_group;")
#define CP_WAIT(n)  asm volatile("cp.async.wait_group %0;" :: "n"(n))

// ---------------------------------------------------------------------------
// Elementwise tf32 rounding pre-pass
// ---------------------------------------------------------------------------
__global__ void round_tf32_kernel(const float* __restrict__ in,
                                  float* __restrict__ out, int n) {
    int i = blockIdx.x * blockDim.x + threadIdx.x;
    if (i < n) out[i] = tf32r(in[i]);
}

// ---------------------------------------------------------------------------
// tf32 tensor-core GEMM (NT): C[m][n] = sum_k A[m][k]*W[n][k] + bias[n]
// BM=BN=128, BK=32, 256 threads (8 warps), warp tile 64x32, double-buffered
// cp.async. Inputs must already be tf32-rounded values.
// ---------------------------------------------------------------------------
#define GS 36                 // smem row stride (32 + 4 pad)
#define GTILE (128*GS)        // floats per stage per operand

__global__ __launch_bounds__(256, 2)
void mma_gemm_nt(const float* __restrict__ A, const float* __restrict__ W,
                 const float* __restrict__ bias, float* __restrict__ C,
                 int M, int N, int K) {
    extern __shared__ float sm[];
    float* As = sm;               // [2][GTILE]
    float* Bs = sm + 2 * GTILE;   // [2][GTILE]

    int tid = threadIdx.x, lane = tid & 31, wid = tid >> 5;
    int g = lane >> 2, t = lane & 3;
    int wm = wid >> 2, wn = wid & 3;   // 2 x 4 warp grid
    int m0 = blockIdx.y * 128, n0 = blockIdx.x * 128;

    float acc[4][4][4];
#pragma unroll
    for (int i = 0; i < 4; i++)
#pragma unroll
        for (int j = 0; j < 4; j++)
#pragma unroll
            for (int e = 0; e < 4; e++) acc[i][j][e] = 0.f;

    const int nk = K / 32;

    // stage loader
    auto loadStage = [&](int st, int k0) {
        float* as = As + st * GTILE;
        float* bs = Bs + st * GTILE;
#pragma unroll
        for (int p = 0; p < 4; p++) {
            int idx = tid + p * 256;
            int row = idx >> 3, c4 = (idx & 7) * 4;
            cpa16(as + row * GS + c4, A + (size_t)(m0 + row) * K + k0 + c4);
            cpa16(bs + row * GS + c4, W + (size_t)(n0 + row) * K + k0 + c4);
        }
    };

    loadStage(0, 0);
    CP_COMMIT();

    for (int kt = 0; kt < nk; kt++) {
        if (kt + 1 < nk) {
            loadStage((kt + 1) & 1, (kt + 1) * 32);
            CP_COMMIT();
            CP_WAIT(1);
        } else {
            CP_WAIT(0);
        }
        __syncthreads();

        const float* as = As + (kt & 1) * GTILE;
        const float* bs = Bs + (kt & 1) * GTILE;
#pragma unroll
        for (int kk = 0; kk < 4; kk++) {
            float af[4][4], bf[4][2];
#pragma unroll
            for (int mf = 0; mf < 4; mf++) {
                int r = wm * 64 + mf * 16;
                af[mf][0] = as[(r + g) * GS + kk * 8 + t];
                af[mf][1] = as[(r + g + 8) * GS + kk * 8 + t];
                af[mf][2] = as[(r + g) * GS + kk * 8 + t + 4];
                af[mf][3] = as[(r + g + 8) * GS + kk * 8 + t + 4];
            }
#pragma unroll
            for (int nf = 0; nf < 4; nf++) {
                int c = wn * 32 + nf * 8;
                bf[nf][0] = bs[(c + g) * GS + kk * 8 + t];
                bf[nf][1] = bs[(c + g) * GS + kk * 8 + t + 4];
            }
#pragma unroll
            for (int mf = 0; mf < 4; mf++)
#pragma unroll
                for (int nf = 0; nf < 4; nf++)
                    mma_tf32(acc[mf][nf], af[mf], bf[nf]);
        }
        __syncthreads();
    }

    // epilogue
#pragma unroll
    for (int mf = 0; mf < 4; mf++) {
        int r0 = m0 + wm * 64 + mf * 16 + g;
        int r1 = r0 + 8;
#pragma unroll
        for (int nf = 0; nf < 4; nf++) {
            int c = n0 + wn * 32 + nf * 8 + 2 * t;
            float bx = bias[c], by = bias[c + 1];
            float2 v0 = make_float2(acc[mf][nf][0] + bx, acc[mf][nf][1] + by);
            float2 v1 = make_float2(acc[mf][nf][2] + bx, acc[mf][nf][3] + by);
            *(float2*)(C + (size_t)r0 * N + c) = v0;
            *(float2*)(C + (size_t)r1 * N + c) = v1;
        }
    }
}

// ---------------------------------------------------------------------------
// RoPE-variant applied in-place to q and k slices of g_qkv (fp32).
// ---------------------------------------------------------------------------
__global__ void rope_kernel(float* __restrict__ qkv) {
    int idx = blockIdx.x * blockDim.x + threadIdx.x;
    const int total = BT_ * H_ * (DH_ / 2);
    if (idx >= total) return;
    int i = idx & 31;
    int h = (idx >> 5) & 15;
    int bt = idx >> 9;
    int t = bt & (T_ - 1);

    float freq = __powf(10000.f, (2.f * (float)i) / (float)DH_);
    float ang = (float)t / freq;
    float c, s;
    __sincosf(ang, &s, &c);

    float* base = qkv + (size_t)bt * QKV_COLS + h * (3 * DH_);
    float e = base[2 * i], o = base[2 * i + 1];
    base[2 * i]     = e * c - o * (1.f - c);
    base[2 * i + 1] = o * s + e * (1.f - s);
    e = base[DH_ + 2 * i];
    o = base[DH_ + 2 * i + 1];
    base[DH_ + 2 * i]     = e * c - o * (1.f - c);
    base[DH_ + 2 * i + 1] = o * s + e * (1.f - s);
}

// ---------------------------------------------------------------------------
// Flash attention with tf32 mma. Block = (b,h, 64-query tile).
// 128 threads (4 warps), each warp owns 16 query rows.
// Br = Bc = 64, DH = 64. Q frags in registers; K,V,P staged in padded smem.
// ---------------------------------------------------------------------------
#define AST 72   // attn smem row stride (64 + 8) -> conflict-free frag reads

__global__ __launch_bounds__(128, 2)
void attn_mma_kernel(const float* __restrict__ qkv, float* __restrict__ y) {
    int bh = blockIdx.y;
    int b = bh >> 4, h = bh & 15;
    int it = gridDim.x - 1 - blockIdx.x;   // heaviest tiles first
    int m0 = it * 64;
    int tid = threadIdx.x, lane = tid & 31, wid = tid >> 5;
    int g = lane >> 2, t = lane & 3;

    extern __shared__ float sm[];
    float* Ks = sm;              // [64][AST]
    float* Vs = Ks + 64 * AST;   // [64][AST]
    float* Ps = Vs + 64 * AST;   // [64][AST]

    const float* base = qkv + (size_t)b * T_ * QKV_COLS + h * (3 * DH_);

    // Q fragments (rows m0 + wid*16 + {g, g+8}), rounded to tf32
    float qf[8][4];
    {
        const float* q0 = base + (size_t)(m0 + wid * 16 + g) * QKV_COLS;
        const float* q1 = base + (size_t)(m0 + wid * 16 + g + 8) * QKV_COLS;
#pragma unroll
        for (int kf = 0; kf < 8; kf++) {
            qf[kf][0] = tf32r(q0[kf * 8 + t]);
            qf[kf][1] = tf32r(q1[kf * 8 + t]);
            qf[kf][2] = tf32r(q0[kf * 8 + t + 4]);
            qf[kf][3] = tf32r(q1[kf * 8 + t + 4]);
        }
    }

    float o[8][4];
#pragma unroll
    for (int nf = 0; nf < 8; nf++)
#pragma unroll
        for (int e = 0; e < 4; e++) o[nf][e] = 0.f;
    float mA = -1e30f, mB = -1e30f, lA = 0.f, lB = 0.f;

    for (int s0 = 0; s0 <= m0; s0 += 64) {
        __syncthreads();   // protect Ks/Vs from previous iteration's readers
        // cooperative K,V tile load (rounded to tf32)
        for (int i = tid; i < 64 * 16; i += 128) {
            int row = i >> 4, c4 = (i & 15) * 4;
            const float* src = base + (size_t)(s0 + row) * QKV_COLS + DH_;  // k
            float4 kv = *(const float4*)(src + c4);
            float4 vv = *(const float4*)(src + DH_ + c4);
            float* kd = Ks + row * AST + c4;
            kd[0] = tf32r(kv.x); kd[1] = tf32r(kv.y);
            kd[2] = tf32r(kv.z); kd[3] = tf32r(kv.w);
            float* vd = Vs + row * AST + c4;
            vd[0] = tf32r(vv.x); vd[1] = tf32r(vv.y);
            vd[2] = tf32r(vv.z); vd[3] = tf32r(vv.w);
        }
        __syncthreads();

        // S = Q @ K^T  (each warp: 16 x 64)
        float s[8][4];
#pragma unroll
        for (int nf = 0; nf < 8; nf++)
#pragma unroll
            for (int e = 0; e < 4; e++) s[nf][e] = 0.f;
#pragma unroll
        for (int kf = 0; kf < 8; kf++) {
#pragma unroll
            for (int nf = 0; nf < 8; nf++) {
                float bf[2];
                bf[0] = Ks[(nf * 8 + g) * AST + kf * 8 + t];
                bf[1] = Ks[(nf * 8 + g) * AST + kf * 8 + t + 4];
                mma_tf32(s[nf], qf[kf], bf);
            }
        }

        // scale + causal mask (only the diagonal tile needs masking)
#pragma unroll
        for (int nf = 0; nf < 8; nf++)
#pragma unroll
            for (int e = 0; e < 4; e++) s[nf][e] *= 0.125f;
        if (s0 == m0) {
            int ra = wid * 16 + g, rb = ra + 8;
#pragma unroll
            for (int nf = 0; nf < 8; nf++) {
                int c0 = nf * 8 + 2 * t, c1 = c0 + 1;
                if (c0 > ra) s[nf][0] = -1e30f;
                if (c1 > ra) s[nf][1] = -1e30f;
                if (c0 > rb) s[nf][2] = -1e30f;
                if (c1 > rb) s[nf][3] = -1e30f;
            }
        }

        // online softmax (rows g and g+8 of this warp's stripe)
        float mtA = -1e30f, mtB = -1e30f;
#pragma unroll
        for (int nf = 0; nf < 8; nf++) {
            mtA = fmaxf(mtA, fmaxf(s[nf][0], s[nf][1]));
            mtB = fmaxf(mtB, fmaxf(s[nf][2], s[nf][3]));
        }
        mtA = fmaxf(mtA, __shfl_xor_sync(0xffffffffu, mtA, 1));
        mtA = fmaxf(mtA, __shfl_xor_sync(0xffffffffu, mtA, 2));
        mtB = fmaxf(mtB, __shfl_xor_sync(0xffffffffu, mtB, 1));
        mtB = fmaxf(mtB, __shfl_xor_sync(0xffffffffu, mtB, 2));
        float mnA = fmaxf(mA, mtA), mnB = fmaxf(mB, mtB);
        float aA = __expf(mA - mnA), aB = __expf(mB - mnB);
        float sA = 0.f, sB = 0.f;
#pragma unroll
        for (int nf = 0; nf < 8; nf++) {
            s[nf][0] = __expf(s[nf][0] - mnA);
            s[nf][1] = __expf(s[nf][1] - mnA);
            s[nf][2] = __expf(s[nf][2] - mnB);
            s[nf][3] = __expf(s[nf][3] - mnB);
            sA += s[nf][0] + s[nf][1];
            sB += s[nf][2] + s[nf][3];
        }
        sA += __shfl_xor_sync(0xffffffffu, sA, 1);
        sA += __shfl_xor_sync(0xffffffffu, sA, 2);
        sB += __shfl_xor_sync(0xffffffffu, sB, 1);
        sB += __shfl_xor_sync(0xffffffffu, sB, 2);
        lA = lA * aA + sA;
        lB = lB * aB + sB;
        mA = mnA; mB = mnB;
#pragma unroll
        for (int nf = 0; nf < 8; nf++) {
            o[nf][0] *= aA; o[nf][1] *= aA;
            o[nf][2] *= aB; o[nf][3] *= aB;
        }

        // P -> smem (re-fragment for PV), rounded to tf32
#pragma unroll
        for (int nf = 0; nf < 8; nf++) {
            int c = nf * 8 + 2 * t;
            float* p0 = Ps + (wid * 16 + g) * AST + c;
            float* p1 = Ps + (wid * 16 + g + 8) * AST + c;
            p0[0] = tf32r(s[nf][0]); p0[1] = tf32r(s[nf][1]);
            p1[0] = tf32r(s[nf][2]); p1[1] = tf32r(s[nf][3]);
        }
        __syncwarp();

        // O += P @ V
#pragma unroll
        for (int kf = 0; kf < 8; kf++) {
            float af[4];
            const float* p0 = Ps + (wid * 16 + g) * AST + kf * 8;
            const float* p1 = Ps + (wid * 16 + g + 8) * AST + kf * 8;
            af[0] = p0[t]; af[1] = p1[t]; af[2] = p0[t + 4]; af[3] = p1[t + 4];
#pragma unroll
            for (int nf = 0; nf < 8; nf++) {
                float bf[2];
                bf[0] = Vs[(kf * 8 + t) * AST + nf * 8 + g];
                bf[1] = Vs[(kf * 8 + t + 4) * AST + nf * 8 + g];
                mma_tf32(o[nf], af, bf);
            }
        }
    }

    // epilogue: normalize, round to tf32 (feeds proj GEMM), store
    float iA = 1.f / lA, iB = 1.f / lB;
    int rA = m0 + wid * 16 + g;
    float* y0 = y + (size_t)(b * T_ + rA) * D_ + h * DH_;
    float* y1 = y + (size_t)(b * T_ + rA + 8) * D_ + h * DH_;
#pragma unroll
    for (int nf = 0; nf < 8; nf++) {
        int c = nf * 8 + 2 * t;
        y0[c]     = tf32r(o[nf][0] * iA);
        y0[c + 1] = tf32r(o[nf][1] * iA);
        y1[c]     = tf32r(o[nf][2] * iB);
        y1[c + 1] = tf32r(o[nf][3] * iB);
    }
}

// ---------------------------------------------------------------------------
// Launch
// ---------------------------------------------------------------------------
extern "C" void kernel_launch(void* const* d_in, const int* in_sizes, int n_in,
                              void* d_out, int out_size) {
    const float* x     = (const float*)d_in[0];
    const float* Wqkv  = (const float*)d_in[1];
    const float* bqkv  = (const float*)d_in[2];
    const float* Wproj = (const float*)d_in[3];
    const float* bproj = (const float*)d_in[4];
    float* out = (float*)d_out;

    float *qkv, *y, *xr, *wqkvr, *wprojr;
    cudaGetSymbolAddress((void**)&qkv, g_qkv);
    cudaGetSymbolAddress((void**)&y, g_y);
    cudaGetSymbolAddress((void**)&xr, g_xr);
    cudaGetSymbolAddress((void**)&wqkvr, g_wqkvr);
    cudaGetSymbolAddress((void**)&wprojr, g_wprojr);

    // 0) tf32-round operands (unbiased rounding; mma itself truncates)
    {
        int n1 = BT_ * D_;
        round_tf32_kernel<<<(n1 + 255) / 256, 256>>>(x, xr, n1);
        int n2 = QKV_COLS * D_;
        round_tf32_kernel<<<(n2 + 255) / 256, 256>>>(Wqkv, wqkvr, n2);
        int n3 = D_ * D_;
        round_tf32_kernel<<<(n3 + 255) / 256, 256>>>(Wproj, wprojr, n3);
    }

    int gemm_smem = 4 * GTILE * (int)sizeof(float); // 73728 B
    cudaFuncSetAttribute(mma_gemm_nt,
                         cudaFuncAttributeMaxDynamicSharedMemorySize, gemm_smem);

    // 1) QKV GEMM
    {
        dim3 grid(QKV_COLS / 128, BT_ / 128);
        mma_gemm_nt<<<grid, 256, gemm_smem>>>(xr, wqkvr, bqkv, qkv,
                                              BT_, QKV_COLS, D_);
    }

    // 2) RoPE
    {
        int total = BT_ * H_ * (DH_ / 2);
        rope_kernel<<<(total + 255) / 256, 256>>>(qkv);
    }

    // 3) Flash attention (tensor cores)
    {
        int smem = 3 * 64 * AST * (int)sizeof(float); // 55296 B
        cudaFuncSetAttribute(attn_mma_kernel,
                             cudaFuncAttributeMaxDynamicSharedMemorySize, smem);
        dim3 grid(T_ / 64, B_ * H_);
        attn_mma_kernel<<<grid, 128, smem>>>(qkv, y);
    }

    // 4) Proj GEMM
    {
        dim3 grid(D_ / 128, BT_ / 128);
        mma_gemm_nt<<<grid, 256, gemm_smem>>>(y, wprojr, bproj, out,
                                              BT_, D_, D_);
    }
}

// round 3
// speedup vs baseline: 4.3586x; 1.1245x over previous
#include <cuda_runtime.h>
#include <cuda_bf16.h>
#include <math.h>
#include <stdint.h>

#define B_  2
#define T_  2048
#define D_  1024
#define H_  16
#define DH_ 64
#define QKV_COLS 3072   // 3*D
#define BT_ (B_*T_)     // 4096

// Scratch (allocation-free rule: __device__ globals)
__device__ float g_qkv[(size_t)BT_ * QKV_COLS];   // 48 MB
__device__ float g_y[(size_t)BT_ * D_];           // 16 MB
__device__ float g_xr[(size_t)BT_ * D_];          // 16 MB (tf32-rounded x)
__device__ float g_wqkvr[(size_t)QKV_COLS * D_];  // 12 MB
__device__ float g_wprojr[(size_t)D_ * D_];       // 4 MB

// ---------------------------------------------------------------------------
// Helpers
// ---------------------------------------------------------------------------
__device__ __forceinline__ float tf32r(float x) {
    uint32_t u;
    asm("cvt.rna.tf32.f32 %0, %1;" : "=r"(u) : "f"(x));
    return __uint_as_float(u);
}

__device__ __forceinline__ void mma_tf32u(float* c, const uint32_t* a, const uint32_t* b) {
    asm volatile(
        "mma.sync.aligned.m16n8k8.row.col.f32.tf32.tf32.f32 "
        "{%0,%1,%2,%3}, {%4,%5,%6,%7}, {%8,%9}, {%0,%1,%2,%3};"
        : "+f"(c[0]), "+f"(c[1]), "+f"(c[2]), "+f"(c[3])
        : "r"(a[0]), "r"(a[1]), "r"(a[2]), "r"(a[3]), "r"(b[0]), "r"(b[1]));
}

__device__ __forceinline__ void ldsm_x4(uint32_t addr, uint32_t* r) {
    asm volatile("ldmatrix.sync.aligned.m8n8.x4.shared.b16 {%0,%1,%2,%3}, [%4];"
                 : "=r"(r[0]), "=r"(r[1]), "=r"(r[2]), "=r"(r[3]) : "r"(addr));
}

__device__ __forceinline__ void cpa16(void* smem, const void* g) {
    uint32_t s = (uint32_t)__cvta_generic_to_shared(smem);
    asm volatile("cp.async.cg.shared.global [%0], [%1], 16;" :: "r"(s), "l"(g));
}
#define CP_COMMIT() asm volatile("cp.async.commit_group;")
#define CP_WAIT(n)  asm volatile("cp.async.wait_group %0;" :: "n"(n))

// ---------------------------------------------------------------------------
// Elementwise tf32 rounding pre-pass
// ---------------------------------------------------------------------------
__global__ void round_tf32_kernel(const float* __restrict__ in,
                                  float* __restrict__ out, int n) {
    int i = blockIdx.x * blockDim.x + threadIdx.x;
    if (i < n) out[i] = tf32r(in[i]);
}

// ---------------------------------------------------------------------------
// tf32 tensor-core GEMM (NT): C[m][n] = sum_k A[m][k]*W[n][k] + bias[n]
// BM=BN=128, BK=16, 256 threads (8 warps 2x4), warp tile 64x32.
// 4-stage cp.async pipeline, ldmatrix fragment loads.
// Inputs must already be tf32-rounded.
// ---------------------------------------------------------------------------
#define GS 20                 // smem row stride in floats (16 + 4 pad) - LDSM conflict-free
#define STAGE (128*GS)        // floats per operand per stage

__global__ __launch_bounds__(256, 2)
void mma_gemm_nt(const float* __restrict__ A, const float* __restrict__ W,
                 const float* __restrict__ bias, float* __restrict__ C,
                 int M, int N, int K) {
    extern __shared__ float sm[];
    float* As = sm;               // [4][STAGE]
    float* Bs = sm + 4 * STAGE;   // [4][STAGE]

    int tid = threadIdx.x, lane = tid & 31, wid = tid >> 5;
    int g = lane >> 2, t = lane & 3;
    int wm = wid >> 2, wn = wid & 3;   // 2 x 4 warp grid
    int m0 = blockIdx.y * 128, n0 = blockIdx.x * 128;

    // LDSM lane-derived offsets
    int lr = lane & 7;
    int sel = lane >> 3;
    // A tiles: m0=(r,kc) m1=(r+8,kc) m2=(r,kc+4) m3=(r+8,kc+4)
    int aRow = lr + (sel & 1) * 8;
    int aCol = (sel >> 1) * 4;
    // B tiles: m0=(n,kc) m1=(n,kc+4) m2=(n+8,kc) m3=(n+8,kc+4)
    int bRow = lr + (sel >> 1) * 8;
    int bCol = (sel & 1) * 4;

    uint32_t asBase = (uint32_t)__cvta_generic_to_shared(As);
    uint32_t bsBase = (uint32_t)__cvta_generic_to_shared(Bs);

    float acc[4][4][4];
#pragma unroll
    for (int i = 0; i < 4; i++)
#pragma unroll
        for (int j = 0; j < 4; j++)
#pragma unroll
            for (int e = 0; e < 4; e++) acc[i][j][e] = 0.f;

    const int nk = K / 16;

    // chunk coords for cp.async (2 chunks per operand per thread)
    int r0c = tid >> 2, c0c = (tid & 3) * 4;          // chunk 0: rows 0..63
    int r1c = r0c + 64;                                // chunk 1: rows 64..127

    auto loadStage = [&](int st, int k0) {
        float* as = As + st * STAGE;
        float* bs = Bs + st * STAGE;
        cpa16(as + r0c * GS + c0c, A + (size_t)(m0 + r0c) * K + k0 + c0c);
        cpa16(as + r1c * GS + c0c, A + (size_t)(m0 + r1c) * K + k0 + c0c);
        cpa16(bs + r0c * GS + c0c, W + (size_t)(n0 + r0c) * K + k0 + c0c);
        cpa16(bs + r1c * GS + c0c, W + (size_t)(n0 + r1c) * K + k0 + c0c);
    };

    loadStage(0, 0);  CP_COMMIT();
    loadStage(1, 16); CP_COMMIT();
    loadStage(2, 32); CP_COMMIT();

    for (int kt = 0; kt < nk; kt++) {
        CP_WAIT(2);
        __syncthreads();
        if (kt + 3 < nk) loadStage((kt + 3) & 3, (kt + 3) * 16);
        CP_COMMIT();

        int st = kt & 3;
        uint32_t aB = asBase + (uint32_t)(st * STAGE) * 4u;
        uint32_t bB = bsBase + (uint32_t)(st * STAGE) * 4u;
#pragma unroll
        for (int kk = 0; kk < 2; kk++) {
            uint32_t af[4][4], bf[4][2];
#pragma unroll
            for (int mf = 0; mf < 4; mf++) {
                uint32_t addr = aB + ((wm * 64 + mf * 16 + aRow) * GS + kk * 8 + aCol) * 4u;
                ldsm_x4(addr, af[mf]);
            }
#pragma unroll
            for (int nfp = 0; nfp < 2; nfp++) {
                uint32_t r4[4];
                uint32_t addr = bB + ((wn * 32 + nfp * 16 + bRow) * GS + kk * 8 + bCol) * 4u;
                ldsm_x4(addr, r4);
                bf[2 * nfp][0] = r4[0]; bf[2 * nfp][1] = r4[1];
                bf[2 * nfp + 1][0] = r4[2]; bf[2 * nfp + 1][1] = r4[3];
            }
#pragma unroll
            for (int mf = 0; mf < 4; mf++)
#pragma unroll
                for (int nf = 0; nf < 4; nf++)
                    mma_tf32u(acc[mf][nf], af[mf], bf[nf]);
        }
    }

    // epilogue
#pragma unroll
    for (int mf = 0; mf < 4; mf++) {
        int r0 = m0 + wm * 64 + mf * 16 + g;
        int r1 = r0 + 8;
#pragma unroll
        for (int nf = 0; nf < 4; nf++) {
            int c = n0 + wn * 32 + nf * 8 + 2 * t;
            float bx = bias[c], by = bias[c + 1];
            float2 v0 = make_float2(acc[mf][nf][0] + bx, acc[mf][nf][1] + by);
            float2 v1 = make_float2(acc[mf][nf][2] + bx, acc[mf][nf][3] + by);
            *(float2*)(C + (size_t)r0 * N + c) = v0;
            *(float2*)(C + (size_t)r1 * N + c) = v1;
        }
    }
}

// ---------------------------------------------------------------------------
// RoPE-variant applied in-place to q,k of g_qkv; output tf32-rounded.
// Also rounds v in-place so attention can cp.async raw values.
// ---------------------------------------------------------------------------
__global__ void rope_kernel(float* __restrict__ qkv) {
    int idx = blockIdx.x * blockDim.x + threadIdx.x;
    const int total = BT_ * H_ * (DH_ / 2);
    if (idx >= total) return;
    int i = idx & 31;
    int h = (idx >> 5) & 15;
    int bt = idx >> 9;
    int t = bt & (T_ - 1);

    float freq = __powf(10000.f, (2.f * (float)i) / (float)DH_);
    float ang = (float)t / freq;
    float c, s;
    __sincosf(ang, &s, &c);

    float* base = qkv + (size_t)bt * QKV_COLS + h * (3 * DH_);
    // q
    float e = base[2 * i], o = base[2 * i + 1];
    base[2 * i]     = tf32r(e * c - o * (1.f - c));
    base[2 * i + 1] = tf32r(o * s + e * (1.f - s));
    // k
    e = base[DH_ + 2 * i];
    o = base[DH_ + 2 * i + 1];
    base[DH_ + 2 * i]     = tf32r(e * c - o * (1.f - c));
    base[DH_ + 2 * i + 1] = tf32r(o * s + e * (1.f - s));
    // v (round only)
    base[2 * DH_ + 2 * i]     = tf32r(base[2 * DH_ + 2 * i]);
    base[2 * DH_ + 2 * i + 1] = tf32r(base[2 * DH_ + 2 * i + 1]);
}

// ---------------------------------------------------------------------------
// Flash attention, tf32 mma. Block = (b,h, 128-query tile), 256 threads
// (8 warps x 16 rows). Bc=64. Double-buffered cp.async K/V staging.
// K frags via ldmatrix; P re-fragmentation via shuffles.
// ---------------------------------------------------------------------------
#define KST 68   // Ks row stride (LDSM conflict-free: 68 mod 32 = 4)
#define VST 72   // Vs row stride (scalar-frag conflict-free: 72 mod 32 = 8)

__global__ __launch_bounds__(256, 1)
void attn_mma_kernel(const float* __restrict__ qkv, float* __restrict__ y) {
    int bh = blockIdx.y;
    int b = bh >> 4, h = bh & 15;
    int it = gridDim.x - 1 - blockIdx.x;   // heaviest tiles first
    int m0 = it * 128;
    int tid = threadIdx.x, lane = tid & 31, wid = tid >> 5;
    int g = lane >> 2, t = lane & 3;

    extern __shared__ float sm[];
    float* Ks = sm;                    // [2][64][KST]
    float* Vs = sm + 2 * 64 * KST;     // [2][64][VST]
    uint32_t ksBase = (uint32_t)__cvta_generic_to_shared(Ks);

    // LDSM offsets for K B-frags (tiles: (n,kc),(n,kc+4),(n+8,kc),(n+8,kc+4))
    int lr = lane & 7, sel = lane >> 3;
    int kbRow = lr + (sel >> 1) * 8;
    int kbCol = (sel & 1) * 4;

    const float* base = qkv + (size_t)b * T_ * QKV_COLS + h * (3 * DH_);

    // Q fragments (rows m0 + wid*16 + {g, g+8}); already tf32-rounded by rope
    uint32_t qf[8][4];
    {
        const float* q0 = base + (size_t)(m0 + wid * 16 + g) * QKV_COLS;
        const float* q1 = base + (size_t)(m0 + wid * 16 + g + 8) * QKV_COLS;
#pragma unroll
        for (int kf = 0; kf < 8; kf++) {
            qf[kf][0] = __float_as_uint(q0[kf * 8 + t]);
            qf[kf][1] = __float_as_uint(q1[kf * 8 + t]);
            qf[kf][2] = __float_as_uint(q0[kf * 8 + t + 4]);
            qf[kf][3] = __float_as_uint(q1[kf * 8 + t + 4]);
        }
    }

    float o[8][4];
#pragma unroll
    for (int nf = 0; nf < 8; nf++)
#pragma unroll
        for (int e = 0; e < 4; e++) o[nf][e] = 0.f;
    float mA = -1e30f, mB = -1e30f, lA = 0.f, lB = 0.f;

    const int nTiles = 2 * it + 2;

    // cp.async staging: K tile 64x64 -> 1024 chunks; V same. 8 chunks/thread.
    int sRow = tid >> 2;                // for pairs of rows (tid 0..255 -> row 0..63 x4 cols)
    auto loadTile = [&](int buf, int s0) {
        float* kd = Ks + buf * 64 * KST;
        float* vd = Vs + buf * 64 * VST;
#pragma unroll
        for (int p = 0; p < 4; p++) {
            int j = tid + p * 256;
            int row = j >> 4, c4 = (j & 15) * 4;
            const float* src = base + (size_t)(s0 + row) * QKV_COLS + DH_;
            cpa16(kd + row * KST + c4, src + c4);
            cpa16(vd + row * VST + c4, src + DH_ + c4);
        }
    };

    loadTile(0, 0);
    CP_COMMIT();

    int lbase = lane & 28;              // g*4
    int l1 = lbase + (t >> 1);
    int tOdd = t & 1;

    for (int ti = 0; ti < nTiles; ti++) {
        int s0 = ti * 64;
        CP_WAIT(0);
        __syncthreads();
        if (ti + 1 < nTiles) loadTile((ti + 1) & 1, s0 + 64);
        CP_COMMIT();

        int buf = ti & 1;
        int rowMin = m0 + wid * 16;

        if (s0 <= rowMin + 15) {  // not fully masked for this warp's stripe
            uint32_t kB = ksBase + (uint32_t)(buf * 64 * KST) * 4u;
            const float* vtile = Vs + buf * 64 * VST;

            // S = Q @ K^T
            float s[8][4];
#pragma unroll
            for (int nf = 0; nf < 8; nf++)
#pragma unroll
                for (int e = 0; e < 4; e++) s[nf][e] = 0.f;
#pragma unroll
            for (int kf = 0; kf < 8; kf++) {
#pragma unroll
                for (int nfp = 0; nfp < 4; nfp++) {
                    uint32_t r4[4];
                    uint32_t addr = kB + ((nfp * 16 + kbRow) * KST + kf * 8 + kbCol) * 4u;
                    ldsm_x4(addr, r4);
                    uint32_t bf0[2] = { r4[0], r4[1] };
                    uint32_t bf1[2] = { r4[2], r4[3] };
                    mma_tf32u(s[2 * nfp], qf[kf], bf0);
                    mma_tf32u(s[2 * nfp + 1], qf[kf], bf1);
                }
            }

            // scale + causal mask
#pragma unroll
            for (int nf = 0; nf < 8; nf++)
#pragma unroll
                for (int e = 0; e < 4; e++) s[nf][e] *= 0.125f;
            if (s0 + 63 > rowMin) {
                int ra = rowMin + g, rb = ra + 8;
#pragma unroll
                for (int nf = 0; nf < 8; nf++) {
                    int c0 = s0 + nf * 8 + 2 * t, c1 = c0 + 1;
                    if (c0 > ra) s[nf][0] = -1e30f;
                    if (c1 > ra) s[nf][1] = -1e30f;
                    if (c0 > rb) s[nf][2] = -1e30f;
                    if (c1 > rb) s[nf][3] = -1e30f;
                }
            }

            // online softmax
            float mtA = -1e30f, mtB = -1e30f;
#pragma unroll
            for (int nf = 0; nf < 8; nf++) {
                mtA = fmaxf(mtA, fmaxf(s[nf][0], s[nf][1]));
                mtB = fmaxf(mtB, fmaxf(s[nf][2], s[nf][3]));
            }
            mtA = fmaxf(mtA, __shfl_xor_sync(0xffffffffu, mtA, 1));
            mtA = fmaxf(mtA, __shfl_xor_sync(0xffffffffu, mtA, 2));
            mtB = fmaxf(mtB, __shfl_xor_sync(0xffffffffu, mtB, 1));
            mtB = fmaxf(mtB, __shfl_xor_sync(0xffffffffu, mtB, 2));
            float mnA = fmaxf(mA, mtA), mnB = fmaxf(mB, mtB);
            float aAl = __expf(mA - mnA), aBl = __expf(mB - mnB);
            float sA = 0.f, sB = 0.f;
#pragma unroll
            for (int nf = 0; nf < 8; nf++) {
                s[nf][0] = tf32r(__expf(s[nf][0] - mnA));
                s[nf][1] = tf32r(__expf(s[nf][1] - mnA));
                s[nf][2] = tf32r(__expf(s[nf][2] - mnB));
                s[nf][3] = tf32r(__expf(s[nf][3] - mnB));
                sA += s[nf][0] + s[nf][1];
                sB += s[nf][2] + s[nf][3];
            }
            sA += __shfl_xor_sync(0xffffffffu, sA, 1);
            sA += __shfl_xor_sync(0xffffffffu, sA, 2);
            sB += __shfl_xor_sync(0xffffffffu, sB, 1);
            sB += __shfl_xor_sync(0xffffffffu, sB, 2);
            lA = lA * aAl + sA;
            lB = lB * aBl + sB;
            mA = mnA; mB = mnB;
#pragma unroll
            for (int nf = 0; nf < 8; nf++) {
                o[nf][0] *= aAl; o[nf][1] *= aAl;
                o[nf][2] *= aBl; o[nf][3] *= aBl;
            }

            // O += P @ V  (P re-fragmented via shuffles)
#pragma unroll
            for (int kf = 0; kf < 8; kf++) {
                float a00 = __shfl_sync(0xffffffffu, s[kf][0], l1);
                float a01 = __shfl_sync(0xffffffffu, s[kf][1], l1);
                float a10 = __shfl_sync(0xffffffffu, s[kf][2], l1);
                float a11 = __shfl_sync(0xffffffffu, s[kf][3], l1);
                float b00 = __shfl_sync(0xffffffffu, s[kf][0], l1 + 2);
                float b01 = __shfl_sync(0xffffffffu, s[kf][1], l1 + 2);
                float b10 = __shfl_sync(0xffffffffu, s[kf][2], l1 + 2);
                float b11 = __shfl_sync(0xffffffffu, s[kf][3], l1 + 2);
                uint32_t af[4];
                af[0] = __float_as_uint(tOdd ? a01 : a00);
                af[1] = __float_as_uint(tOdd ? a11 : a10);
                af[2] = __float_as_uint(tOdd ? b01 : b00);
                af[3] = __float_as_uint(tOdd ? b11 : b10);
                const float* v0 = vtile + (kf * 8 + t) * VST;
                const float* v1 = vtile + (kf * 8 + t + 4) * VST;
#pragma unroll
                for (int nf = 0; nf < 8; nf++) {
                    uint32_t bf[2];
                    bf[0] = __float_as_uint(v0[nf * 8 + g]);
                    bf[1] = __float_as_uint(v1[nf * 8 + g]);
                    mma_tf32u(o[nf], af, bf);
                }
            }
        }
    }

    // epilogue: normalize, round (feeds proj GEMM), store
    float iA = 1.f / lA, iB = 1.f / lB;
    int rA = m0 + wid * 16 + g;
    float* y0 = y + (size_t)(b * T_ + rA) * D_ + h * DH_;
    float* y1 = y + (size_t)(b * T_ + rA + 8) * D_ + h * DH_;
#pragma unroll
    for (int nf = 0; nf < 8; nf++) {
        int c = nf * 8 + 2 * t;
        y0[c]     = tf32r(o[nf][0] * iA);
        y0[c + 1] = tf32r(o[nf][1] * iA);
        y1[c]     = tf32r(o[nf][2] * iB);
        y1[c + 1] = tf32r(o[nf][3] * iB);
    }
    (void)sRow;
}

// ---------------------------------------------------------------------------
// Launch
// ---------------------------------------------------------------------------
extern "C" void kernel_launch(void* const* d_in, const int* in_sizes, int n_in,
                              void* d_out, int out_size) {
    const float* x     = (const float*)d_in[0];
    const float* Wqkv  = (const float*)d_in[1];
    const float* bqkv  = (const float*)d_in[2];
    const float* Wproj = (const float*)d_in[3];
    const float* bproj = (const float*)d_in[4];
    float* out = (float*)d_out;

    float *qkv, *y, *xr, *wqkvr, *wprojr;
    cudaGetSymbolAddress((void**)&qkv, g_qkv);
    cudaGetSymbolAddress((void**)&y, g_y);
    cudaGetSymbolAddress((void**)&xr, g_xr);
    cudaGetSymbolAddress((void**)&wqkvr, g_wqkvr);
    cudaGetSymbolAddress((void**)&wprojr, g_wprojr);

    // 0) tf32-round GEMM operands
    {
        int n1 = BT_ * D_;
        round_tf32_kernel<<<(n1 + 255) / 256, 256>>>(x, xr, n1);
        int n2 = QKV_COLS * D_;
        round_tf32_kernel<<<(n2 + 255) / 256, 256>>>(Wqkv, wqkvr, n2);
        int n3 = D_ * D_;
        round_tf32_kernel<<<(n3 + 255) / 256, 256>>>(Wproj, wprojr, n3);
    }

    int gemm_smem = 8 * STAGE * (int)sizeof(float); // 81920 B
    cudaFuncSetAttribute(mma_gemm_nt,
                         cudaFuncAttributeMaxDynamicSharedMemorySize, gemm_smem);

    // 1) QKV GEMM
    {
        dim3 grid(QKV_COLS / 128, BT_ / 128);
        mma_gemm_nt<<<grid, 256, gemm_smem>>>(xr, wqkvr, bqkv, qkv,
                                              BT_, QKV_COLS, D_);
    }

    // 2) RoPE (+ tf32 rounding of q,k,v)
    {
        int total = BT_ * H_ * (DH_ / 2);
        rope_kernel<<<(total + 255) / 256, 256>>>(qkv);
    }

    // 3) Flash attention
    {
        int smem = (2 * 64 * KST + 2 * 64 * VST) * (int)sizeof(float); // 71680 B
        cudaFuncSetAttribute(attn_mma_kernel,
                             cudaFuncAttributeMaxDynamicSharedMemorySize, smem);
        dim3 grid(T_ / 128, B_ * H_);
        attn_mma_kernel<<<grid, 256, smem>>>(qkv, y);
    }

    // 4) Proj GEMM
    {
        dim3 grid(D_ / 128, BT_ / 128);
        mma_gemm_nt<<<grid, 256, gemm_smem>>>(y, wprojr, bproj, out,
                                              BT_, D_, D_);
    }
}

// round 5
// speedup vs baseline: 4.3964x; 1.0087x over previous
#include <cuda_runtime.h>
#include <cuda_bf16.h>
#include <math.h>
#include <stdint.h>

#define B_  2
#define T_  2048
#define D_  1024
#define H_  16
#define DH_ 64
#define QKV_COLS 3072   // 3*D
#define BT_ (B_*T_)     // 4096

// Scratch (allocation-free rule: __device__ globals)
__device__ float g_qkv[(size_t)BT_ * QKV_COLS];   // 48 MB
__device__ float g_y[(size_t)BT_ * D_];           // 16 MB
__device__ float g_xr[(size_t)BT_ * D_];          // 16 MB (tf32-rounded x)
__device__ float g_wqkvr[(size_t)QKV_COLS * D_];  // 12 MB
__device__ float g_wprojr[(size_t)D_ * D_];       // 4 MB

// ---------------------------------------------------------------------------
// Helpers
// ---------------------------------------------------------------------------
__device__ __forceinline__ float tf32r(float x) {
    uint32_t u;
    asm("cvt.rna.tf32.f32 %0, %1;" : "=r"(u) : "f"(x));
    return __uint_as_float(u);
}

__device__ __forceinline__ void mma_tf32u(float* c, const uint32_t* a, const uint32_t* b) {
    asm volatile(
        "mma.sync.aligned.m16n8k8.row.col.f32.tf32.tf32.f32 "
        "{%0,%1,%2,%3}, {%4,%5,%6,%7}, {%8,%9}, {%0,%1,%2,%3};"
        : "+f"(c[0]), "+f"(c[1]), "+f"(c[2]), "+f"(c[3])
        : "r"(a[0]), "r"(a[1]), "r"(a[2]), "r"(a[3]), "r"(b[0]), "r"(b[1]));
}

__device__ __forceinline__ void ldsm_x4(uint32_t addr, uint32_t* r) {
    asm volatile("ldmatrix.sync.aligned.m8n8.x4.shared.b16 {%0,%1,%2,%3}, [%4];"
                 : "=r"(r[0]), "=r"(r[1]), "=r"(r[2]), "=r"(r[3]) : "r"(addr));
}

__device__ __forceinline__ void cpa16(void* smem, const void* g) {
    uint32_t s = (uint32_t)__cvta_generic_to_shared(smem);
    asm volatile("cp.async.cg.shared.global [%0], [%1], 16;" :: "r"(s), "l"(g));
}
#define CP_COMMIT() asm volatile("cp.async.commit_group;")
#define CP_WAIT(n)  asm volatile("cp.async.wait_group %0;" :: "n"(n))

// ---------------------------------------------------------------------------
// Elementwise tf32 rounding pre-pass
// ---------------------------------------------------------------------------
__global__ void round_tf32_kernel(const float* __restrict__ in,
                                  float* __restrict__ out, int n) {
    int i = blockIdx.x * blockDim.x + threadIdx.x;
    if (i < n) out[i] = tf32r(in[i]);
}

// ---------------------------------------------------------------------------
// tf32 tensor-core GEMM v2 (NT): C[m][n] = sum_k A[m][k]*W[n][k] + bias[n]
// 4 warps (2x2), warp tile 64x64, CTA tile 128x128, BK=32,
// 3-stage cp.async ring, ldmatrix fragment loads.
// smem bytes/MMA = 187 (vs 250 in v1) -> ceiling ~68% tensor.
// Inputs must already be tf32-rounded.
// ---------------------------------------------------------------------------
#define GS 36                 // smem row stride in floats (32 + 4 pad)
#define STG (2*128*GS)        // floats per stage (A tile + B tile)

__global__ __launch_bounds__(128, 2)
void mma_gemm_v2(const float* __restrict__ A, const float* __restrict__ W,
                 const float* __restrict__ bias, float* __restrict__ C,
                 int M, int N, int K) {
    extern __shared__ float sm[];

    int tid = threadIdx.x, lane = tid & 31, wid = tid >> 5;
    int g = lane >> 2, t = lane & 3;
    int wm = wid >> 1, wn = wid & 1;   // 2 x 2 warp grid
    int m0 = blockIdx.y * 128, n0 = blockIdx.x * 128;

    // LDSM lane-derived offsets
    int lr = lane & 7, sel = lane >> 3;
    int aRow = lr + (sel & 1) * 8;     // A tiles: (r,kc),(r+8,kc),(r,kc+4),(r+8,kc+4)
    int aCol = (sel >> 1) * 4;
    int bRow = lr + (sel >> 1) * 8;    // B tiles: (n,kc),(n,kc+4),(n+8,kc),(n+8,kc+4)
    int bCol = (sel & 1) * 4;

    uint32_t smBase = (uint32_t)__cvta_generic_to_shared(sm);

    float acc[4][8][4];
#pragma unroll
    for (int i = 0; i < 4; i++)
#pragma unroll
        for (int j = 0; j < 8; j++)
#pragma unroll
            for (int e = 0; e < 4; e++) acc[i][j][e] = 0.f;

    const int nk = K / 32;

    // stage loader: A 128x32 + B 128x32, 8 16B-chunks per thread per operand
    auto loadStage = [&](int st, int kt) {
        float* as = sm + st * STG;
        float* bs = as + 128 * GS;
        int k0 = kt * 32;
#pragma unroll
        for (int p = 0; p < 8; p++) {
            int idx = tid + p * 128;
            int row = idx >> 3, c4 = (idx & 7) * 4;
            cpa16(as + row * GS + c4, A + (size_t)(m0 + row) * K + k0 + c4);
            cpa16(bs + row * GS + c4, W + (size_t)(n0 + row) * K + k0 + c4);
        }
        CP_COMMIT();
    };

    loadStage(0, 0);
    loadStage(1, 1);

    for (int kt = 0; kt < nk; kt++) {
        if (kt + 2 < nk) { CP_WAIT(1); } else { CP_WAIT(0); }
        __syncthreads();                       // stage kt resident for all; prev readers done
        if (kt + 2 < nk) loadStage((kt + 2) % 3, kt + 2);

        int st = kt % 3;
        uint32_t aB = smBase + (uint32_t)(st * STG) * 4u;
        uint32_t bB = aB + (uint32_t)(128 * GS) * 4u;
#pragma unroll
        for (int kk = 0; kk < 4; kk++) {
            uint32_t af[4][4], bf[8][2];
#pragma unroll
            for (int mf = 0; mf < 4; mf++)
                ldsm_x4(aB + ((wm * 64 + mf * 16 + aRow) * GS + kk * 8 + aCol) * 4u, af[mf]);
#pragma unroll
            for (int nfp = 0; nfp < 4; nfp++) {
                uint32_t r4[4];
                ldsm_x4(bB + ((wn * 64 + nfp * 16 + bRow) * GS + kk * 8 + bCol) * 4u, r4);
                bf[2 * nfp][0] = r4[0]; bf[2 * nfp][1] = r4[1];
                bf[2 * nfp + 1][0] = r4[2]; bf[2 * nfp + 1][1] = r4[3];
            }
#pragma unroll
            for (int mf = 0; mf < 4; mf++)
#pragma unroll
                for (int nf = 0; nf < 8; nf++)
                    mma_tf32u(acc[mf][nf], af[mf], bf[nf]);
        }
    }

    // epilogue
#pragma unroll
    for (int mf = 0; mf < 4; mf++) {
        int r0 = m0 + wm * 64 + mf * 16 + g;
        int r1 = r0 + 8;
#pragma unroll
        for (int nf = 0; nf < 8; nf++) {
            int c = n0 + wn * 64 + (nf >> 1) * 16 + (nf & 1) * 8 + 2 * t;
            float bx = bias[c], by = bias[c + 1];
            float2 v0 = make_float2(acc[mf][nf][0] + bx, acc[mf][nf][1] + by);
            float2 v1 = make_float2(acc[mf][nf][2] + bx, acc[mf][nf][3] + by);
            *(float2*)(C + (size_t)r0 * N + c) = v0;
            *(float2*)(C + (size_t)r1 * N + c) = v1;
        }
    }
}

// ---------------------------------------------------------------------------
// RoPE-variant applied in-place to q,k of g_qkv; output tf32-rounded.
// Also rounds v in-place so attention can cp.async raw values.
// ---------------------------------------------------------------------------
__global__ void rope_kernel(float* __restrict__ qkv) {
    int idx = blockIdx.x * blockDim.x + threadIdx.x;
    const int total = BT_ * H_ * (DH_ / 2);
    if (idx >= total) return;
    int i = idx & 31;
    int h = (idx >> 5) & 15;
    int bt = idx >> 9;
    int t = bt & (T_ - 1);

    float freq = __powf(10000.f, (2.f * (float)i) / (float)DH_);
    float ang = (float)t / freq;
    float c, s;
    __sincosf(ang, &s, &c);

    float* base = qkv + (size_t)bt * QKV_COLS + h * (3 * DH_);
    float e = base[2 * i], o = base[2 * i + 1];
    base[2 * i]     = tf32r(e * c - o * (1.f - c));
    base[2 * i + 1] = tf32r(o * s + e * (1.f - s));
    e = base[DH_ + 2 * i];
    o = base[DH_ + 2 * i + 1];
    base[DH_ + 2 * i]     = tf32r(e * c - o * (1.f - c));
    base[DH_ + 2 * i + 1] = tf32r(o * s + e * (1.f - s));
    base[2 * DH_ + 2 * i]     = tf32r(base[2 * DH_ + 2 * i]);
    base[2 * DH_ + 2 * i + 1] = tf32r(base[2 * DH_ + 2 * i + 1]);
}

// ---------------------------------------------------------------------------
// Flash attention, tf32 mma (unchanged from R3 - known good).
// ---------------------------------------------------------------------------
#define KST 68
#define VST 72

__global__ __launch_bounds__(256, 1)
void attn_mma_kernel(const float* __restrict__ qkv, float* __restrict__ y) {
    int bh = blockIdx.y;
    int b = bh >> 4, h = bh & 15;
    int it = gridDim.x - 1 - blockIdx.x;
    int m0 = it * 128;
    int tid = threadIdx.x, lane = tid & 31, wid = tid >> 5;
    int g = lane >> 2, t = lane & 3;

    extern __shared__ float sm[];
    float* Ks = sm;
    float* Vs = sm + 2 * 64 * KST;
    uint32_t ksBase = (uint32_t)__cvta_generic_to_shared(Ks);

    int lr = lane & 7, sel = lane >> 3;
    int kbRow = lr + (sel >> 1) * 8;
    int kbCol = (sel & 1) * 4;

    const float* base = qkv + (size_t)b * T_ * QKV_COLS + h * (3 * DH_);

    uint32_t qf[8][4];
    {
        const float* q0 = base + (size_t)(m0 + wid * 16 + g) * QKV_COLS;
        const float* q1 = base + (size_t)(m0 + wid * 16 + g + 8) * QKV_COLS;
#pragma unroll
        for (int kf = 0; kf < 8; kf++) {
            qf[kf][0] = __float_as_uint(q0[kf * 8 + t]);
            qf[kf][1] = __float_as_uint(q1[kf * 8 + t]);
            qf[kf][2] = __float_as_uint(q0[kf * 8 + t + 4]);
            qf[kf][3] = __float_as_uint(q1[kf * 8 + t + 4]);
        }
    }

    float o[8][4];
#pragma unroll
    for (int nf = 0; nf < 8; nf++)
#pragma unroll
        for (int e = 0; e < 4; e++) o[nf][e] = 0.f;
    float mA = -1e30f, mB = -1e30f, lA = 0.f, lB = 0.f;

    const int nTiles = 2 * it + 2;

    auto loadTile = [&](int buf, int s0) {
        float* kd = Ks + buf * 64 * KST;
        float* vd = Vs + buf * 64 * VST;
#pragma unroll
        for (int p = 0; p < 4; p++) {
            int j = tid + p * 256;
            int row = j >> 4, c4 = (j & 15) * 4;
            const float* src = base + (size_t)(s0 + row) * QKV_COLS + DH_;
            cpa16(kd + row * KST + c4, src + c4);
            cpa16(vd + row * VST + c4, src + DH_ + c4);
        }
    };

    loadTile(0, 0);
    CP_COMMIT();

    int lbase = lane & 28;
    int l1 = lbase + (t >> 1);
    int tOdd = t & 1;

    for (int ti = 0; ti < nTiles; ti++) {
        int s0 = ti * 64;
        CP_WAIT(0);
        __syncthreads();
        if (ti + 1 < nTiles) loadTile((ti + 1) & 1, s0 + 64);
        CP_COMMIT();

        int buf = ti & 1;
        int rowMin = m0 + wid * 16;

        if (s0 <= rowMin + 15) {
            uint32_t kB = ksBase + (uint32_t)(buf * 64 * KST) * 4u;
            const float* vtile = Vs + buf * 64 * VST;

            float s[8][4];
#pragma unroll
            for (int nf = 0; nf < 8; nf++)
#pragma unroll
                for (int e = 0; e < 4; e++) s[nf][e] = 0.f;
#pragma unroll
            for (int kf = 0; kf < 8; kf++) {
#pragma unroll
                for (int nfp = 0; nfp < 4; nfp++) {
                    uint32_t r4[4];
                    uint32_t addr = kB + ((nfp * 16 + kbRow) * KST + kf * 8 + kbCol) * 4u;
                    ldsm_x4(addr, r4);
                    uint32_t bf0[2] = { r4[0], r4[1] };
                    uint32_t bf1[2] = { r4[2], r4[3] };
                    mma_tf32u(s[2 * nfp], qf[kf], bf0);
                    mma_tf32u(s[2 * nfp + 1], qf[kf], bf1);
                }
            }

#pragma unroll
            for (int nf = 0; nf < 8; nf++)
#pragma unroll
                for (int e = 0; e < 4; e++) s[nf][e] *= 0.125f;
            if (s0 + 63 > rowMin) {
                int ra = rowMin + g, rb = ra + 8;
#pragma unroll
                for (int nf = 0; nf < 8; nf++) {
                    int c0 = s0 + nf * 8 + 2 * t, c1 = c0 + 1;
                    if (c0 > ra) s[nf][0] = -1e30f;
                    if (c1 > ra) s[nf][1] = -1e30f;
                    if (c0 > rb) s[nf][2] = -1e30f;
                    if (c1 > rb) s[nf][3] = -1e30f;
                }
            }

            float mtA = -1e30f, mtB = -1e30f;
#pragma unroll
            for (int nf = 0; nf < 8; nf++) {
                mtA = fmaxf(mtA, fmaxf(s[nf][0], s[nf][1]));
                mtB = fmaxf(mtB, fmaxf(s[nf][2], s[nf][3]));
            }
            mtA = fmaxf(mtA, __shfl_xor_sync(0xffffffffu, mtA, 1));
            mtA = fmaxf(mtA, __shfl_xor_sync(0xffffffffu, mtA, 2));
            mtB = fmaxf(mtB, __shfl_xor_sync(0xffffffffu, mtB, 1));
            mtB = fmaxf(mtB, __shfl_xor_sync(0xffffffffu, mtB, 2));
            float mnA = fmaxf(mA, mtA), mnB = fmaxf(mB, mtB);
            float aAl = __expf(mA - mnA), aBl = __expf(mB - mnB);
            float sA = 0.f, sB = 0.f;
#pragma unroll
            for (int nf = 0; nf < 8; nf++) {
                s[nf][0] = tf32r(__expf(s[nf][0] - mnA));
                s[nf][1] = tf32r(__expf(s[nf][1] - mnA));
                s[nf][2] = tf32r(__expf(s[nf][2] - mnB));
                s[nf][3] = tf32r(__expf(s[nf][3] - mnB));
                sA += s[nf][0] + s[nf][1];
                sB += s[nf][2] + s[nf][3];
            }
            sA += __shfl_xor_sync(0xffffffffu, sA, 1);
            sA += __shfl_xor_sync(0xffffffffu, sA, 2);
            sB += __shfl_xor_sync(0xffffffffu, sB, 1);
            sB += __shfl_xor_sync(0xffffffffu, sB, 2);
            lA = lA * aAl + sA;
            lB = lB * aBl + sB;
            mA = mnA; mB = mnB;
#pragma unroll
            for (int nf = 0; nf < 8; nf++) {
                o[nf][0] *= aAl; o[nf][1] *= aAl;
                o[nf][2] *= aBl; o[nf][3] *= aBl;
            }

#pragma unroll
            for (int kf = 0; kf < 8; kf++) {
                float a00 = __shfl_sync(0xffffffffu, s[kf][0], l1);
                float a01 = __shfl_sync(0xffffffffu, s[kf][1], l1);
                float a10 = __shfl_sync(0xffffffffu, s[kf][2], l1);
                float a11 = __shfl_sync(0xffffffffu, s[kf][3], l1);
                float b00 = __shfl_sync(0xffffffffu, s[kf][0], l1 + 2);
                float b01 = __shfl_sync(0xffffffffu, s[kf][1], l1 + 2);
                float b10 = __shfl_sync(0xffffffffu, s[kf][2], l1 + 2);
                float b11 = __shfl_sync(0xffffffffu, s[kf][3], l1 + 2);
                uint32_t af[4];
                af[0] = __float_as_uint(tOdd ? a01 : a00);
                af[1] = __float_as_uint(tOdd ? a11 : a10);
                af[2] = __float_as_uint(tOdd ? b01 : b00);
                af[3] = __float_as_uint(tOdd ? b11 : b10);
                const float* v0 = vtile + (kf * 8 + t) * VST;
                const float* v1 = vtile + (kf * 8 + t + 4) * VST;
#pragma unroll
                for (int nf = 0; nf < 8; nf++) {
                    uint32_t bf[2];
                    bf[0] = __float_as_uint(v0[nf * 8 + g]);
                    bf[1] = __float_as_uint(v1[nf * 8 + g]);
                    mma_tf32u(o[nf], af, bf);
                }
            }
        }
    }

    float iA = 1.f / lA, iB = 1.f / lB;
    int rA = m0 + wid * 16 + g;
    float* y0 = y + (size_t)(b * T_ + rA) * D_ + h * DH_;
    float* y1 = y + (size_t)(b * T_ + rA + 8) * D_ + h * DH_;
#pragma unroll
    for (int nf = 0; nf < 8; nf++) {
        int c = nf * 8 + 2 * t;
        y0[c]     = tf32r(o[nf][0] * iA);
        y0[c + 1] = tf32r(o[nf][1] * iA);
        y1[c]     = tf32r(o[nf][2] * iB);
        y1[c + 1] = tf32r(o[nf][3] * iB);
    }
}

// ---------------------------------------------------------------------------
// Launch
// ---------------------------------------------------------------------------
extern "C" void kernel_launch(void* const* d_in, const int* in_sizes, int n_in,
                              void* d_out, int out_size) {
    const float* x     = (const float*)d_in[0];
    const float* Wqkv  = (const float*)d_in[1];
    const float* bqkv  = (const float*)d_in[2];
    const float* Wproj = (const float*)d_in[3];
    const float* bproj = (const float*)d_in[4];
    float* out = (float*)d_out;

    float *qkv, *y, *xr, *wqkvr, *wprojr;
    cudaGetSymbolAddress((void**)&qkv, g_qkv);
    cudaGetSymbolAddress((void**)&y, g_y);
    cudaGetSymbolAddress((void**)&xr, g_xr);
    cudaGetSymbolAddress((void**)&wqkvr, g_wqkvr);
    cudaGetSymbolAddress((void**)&wprojr, g_wprojr);

    // 0) tf32-round GEMM operands
    {
        int n1 = BT_ * D_;
        round_tf32_kernel<<<(n1 + 255) / 256, 256>>>(x, xr, n1);
        int n2 = QKV_COLS * D_;
        round_tf32_kernel<<<(n2 + 255) / 256, 256>>>(Wqkv, wqkvr, n2);
        int n3 = D_ * D_;
        round_tf32_kernel<<<(n3 + 255) / 256, 256>>>(Wproj, wprojr, n3);
    }

    int gemm_smem = 3 * STG * (int)sizeof(float); // 110592 B
    cudaFuncSetAttribute(mma_gemm_v2,
                         cudaFuncAttributeMaxDynamicSharedMemorySize, gemm_smem);

    // 1) QKV GEMM
    {
        dim3 grid(QKV_COLS / 128, BT_ / 128);   // (24, 32)
        mma_gemm_v2<<<grid, 128, gemm_smem>>>(xr, wqkvr, bqkv, qkv,
                                              BT_, QKV_COLS, D_);
    }

    // 2) RoPE (+ tf32 rounding of q,k,v)
    {
        int total = BT_ * H_ * (DH_ / 2);
        rope_kernel<<<(total + 255) / 256, 256>>>(qkv);
    }

    // 3) Flash attention
    {
        int smem = (2 * 64 * KST + 2 * 64 * VST) * (int)sizeof(float); // 71680
        cudaFuncSetAttribute(attn_mma_kernel,
                             cudaFuncAttributeMaxDynamicSharedMemorySize, smem);
        dim3 grid(T_ / 128, B_ * H_);
        attn_mma_kernel<<<grid, 256, smem>>>(qkv, y);
    }

    // 4) Proj GEMM
    {
        dim3 grid(D_ / 128, BT_ / 128);         // (8, 32)
        mma_gemm_v2<<<grid, 128, gemm_smem>>>(y, wprojr, bproj, out,
                                              BT_, D_, D_);
    }
}

// round 6
// speedup vs baseline: 5.3961x; 1.2274x over previous
#include <cuda_runtime.h>
#include <cuda_fp16.h>
#include <cuda_bf16.h>
#include <math.h>
#include <stdint.h>

#define B_  2
#define T_  2048
#define D_  1024
#define H_  16
#define DH_ 64
#define QKV_COLS 3072   // 3*D
#define BT_ (B_*T_)     // 4096

// Scratch (allocation-free rule: __device__ globals)
__device__ float g_qkv[(size_t)BT_ * QKV_COLS];   // 48 MB
__device__ float g_y[(size_t)BT_ * D_];           // 16 MB
__device__ float g_xr[(size_t)BT_ * D_];          // 16 MB
__device__ float g_wqkvr[(size_t)QKV_COLS * D_];  // 12 MB
__device__ float g_wprojr[(size_t)D_ * D_];       // 4 MB
__device__ __half g_qh[(size_t)B_ * H_ * T_ * DH_];  // 8 MB  (scaled: *0.125*log2e)
__device__ __half g_kh[(size_t)B_ * H_ * T_ * DH_];  // 8 MB
__device__ __half g_vh[(size_t)B_ * H_ * T_ * DH_];  // 8 MB

// ---------------------------------------------------------------------------
// Helpers
// ---------------------------------------------------------------------------
__device__ __forceinline__ float tf32r(float x) {
    uint32_t u;
    asm("cvt.rna.tf32.f32 %0, %1;" : "=r"(u) : "f"(x));
    return __uint_as_float(u);
}
__device__ __forceinline__ float ex2f(float x) {
    float r;
    asm("ex2.approx.f32 %0, %1;" : "=f"(r) : "f"(x));
    return r;
}
__device__ __forceinline__ void mma_tf32u(float* c, const uint32_t* a, const uint32_t* b) {
    asm volatile(
        "mma.sync.aligned.m16n8k8.row.col.f32.tf32.tf32.f32 "
        "{%0,%1,%2,%3}, {%4,%5,%6,%7}, {%8,%9}, {%0,%1,%2,%3};"
        : "+f"(c[0]), "+f"(c[1]), "+f"(c[2]), "+f"(c[3])
        : "r"(a[0]), "r"(a[1]), "r"(a[2]), "r"(a[3]), "r"(b[0]), "r"(b[1]));
}
__device__ __forceinline__ void mma_f16(float* c, const uint32_t* a, const uint32_t* b) {
    asm volatile(
        "mma.sync.aligned.m16n8k16.row.col.f32.f16.f16.f32 "
        "{%0,%1,%2,%3}, {%4,%5,%6,%7}, {%8,%9}, {%0,%1,%2,%3};"
        : "+f"(c[0]), "+f"(c[1]), "+f"(c[2]), "+f"(c[3])
        : "r"(a[0]), "r"(a[1]), "r"(a[2]), "r"(a[3]), "r"(b[0]), "r"(b[1]));
}
__device__ __forceinline__ void ldsm_x4(uint32_t addr, uint32_t* r) {
    asm volatile("ldmatrix.sync.aligned.m8n8.x4.shared.b16 {%0,%1,%2,%3}, [%4];"
                 : "=r"(r[0]), "=r"(r[1]), "=r"(r[2]), "=r"(r[3]) : "r"(addr));
}
__device__ __forceinline__ void ldsm_x4t(uint32_t addr, uint32_t* r) {
    asm volatile("ldmatrix.sync.aligned.m8n8.x4.trans.shared.b16 {%0,%1,%2,%3}, [%4];"
                 : "=r"(r[0]), "=r"(r[1]), "=r"(r[2]), "=r"(r[3]) : "r"(addr));
}
__device__ __forceinline__ void cpa16(void* smem, const void* g) {
    uint32_t s = (uint32_t)__cvta_generic_to_shared(smem);
    asm volatile("cp.async.cg.shared.global [%0], [%1], 16;" :: "r"(s), "l"(g));
}
#define CP_COMMIT() asm volatile("cp.async.commit_group;")
#define CP_WAIT(n)  asm volatile("cp.async.wait_group %0;" :: "n"(n))

// ---------------------------------------------------------------------------
// Elementwise tf32 rounding pre-pass
// ---------------------------------------------------------------------------
__global__ void round_tf32_kernel(const float* __restrict__ in,
                                  float* __restrict__ out, int n) {
    int i = blockIdx.x * blockDim.x + threadIdx.x;
    if (i < n) out[i] = tf32r(in[i]);
}

// ---------------------------------------------------------------------------
// tf32 tensor-core GEMM (NT): unchanged from R5 (at legacy-HMMA HW cap).
// ---------------------------------------------------------------------------
#define GS 36
#define STG (2*128*GS)

__global__ __launch_bounds__(128, 2)
void mma_gemm_v2(const float* __restrict__ A, const float* __restrict__ W,
                 const float* __restrict__ bias, float* __restrict__ C,
                 int M, int N, int K) {
    extern __shared__ float sm[];

    int tid = threadIdx.x, lane = tid & 31, wid = tid >> 5;
    int g = lane >> 2, t = lane & 3;
    int wm = wid >> 1, wn = wid & 1;
    int m0 = blockIdx.y * 128, n0 = blockIdx.x * 128;

    int lr = lane & 7, sel = lane >> 3;
    int aRow = lr + (sel & 1) * 8;
    int aCol = (sel >> 1) * 4;
    int bRow = lr + (sel >> 1) * 8;
    int bCol = (sel & 1) * 4;

    uint32_t smBase = (uint32_t)__cvta_generic_to_shared(sm);

    float acc[4][8][4];
#pragma unroll
    for (int i = 0; i < 4; i++)
#pragma unroll
        for (int j = 0; j < 8; j++)
#pragma unroll
            for (int e = 0; e < 4; e++) acc[i][j][e] = 0.f;

    const int nk = K / 32;

    auto loadStage = [&](int st, int kt) {
        float* as = sm + st * STG;
        float* bs = as + 128 * GS;
        int k0 = kt * 32;
#pragma unroll
        for (int p = 0; p < 8; p++) {
            int idx = tid + p * 128;
            int row = idx >> 3, c4 = (idx & 7) * 4;
            cpa16(as + row * GS + c4, A + (size_t)(m0 + row) * K + k0 + c4);
            cpa16(bs + row * GS + c4, W + (size_t)(n0 + row) * K + k0 + c4);
        }
        CP_COMMIT();
    };

    loadStage(0, 0);
    loadStage(1, 1);

    for (int kt = 0; kt < nk; kt++) {
        if (kt + 2 < nk) { CP_WAIT(1); } else { CP_WAIT(0); }
        __syncthreads();
        if (kt + 2 < nk) loadStage((kt + 2) % 3, kt + 2);

        int st = kt % 3;
        uint32_t aB = smBase + (uint32_t)(st * STG) * 4u;
        uint32_t bB = aB + (uint32_t)(128 * GS) * 4u;
#pragma unroll
        for (int kk = 0; kk < 4; kk++) {
            uint32_t af[4][4], bf[8][2];
#pragma unroll
            for (int mf = 0; mf < 4; mf++)
                ldsm_x4(aB + ((wm * 64 + mf * 16 + aRow) * GS + kk * 8 + aCol) * 4u, af[mf]);
#pragma unroll
            for (int nfp = 0; nfp < 4; nfp++) {
                uint32_t r4[4];
                ldsm_x4(bB + ((wn * 64 + nfp * 16 + bRow) * GS + kk * 8 + bCol) * 4u, r4);
                bf[2 * nfp][0] = r4[0]; bf[2 * nfp][1] = r4[1];
                bf[2 * nfp + 1][0] = r4[2]; bf[2 * nfp + 1][1] = r4[3];
            }
#pragma unroll
            for (int mf = 0; mf < 4; mf++)
#pragma unroll
                for (int nf = 0; nf < 8; nf++)
                    mma_tf32u(acc[mf][nf], af[mf], bf[nf]);
        }
    }

#pragma unroll
    for (int mf = 0; mf < 4; mf++) {
        int r0 = m0 + wm * 64 + mf * 16 + g;
        int r1 = r0 + 8;
#pragma unroll
        for (int nf = 0; nf < 8; nf++) {
            int c = n0 + wn * 64 + (nf >> 1) * 16 + (nf & 1) * 8 + 2 * t;
            float bx = bias[c], by = bias[c + 1];
            float2 v0 = make_float2(acc[mf][nf][0] + bx, acc[mf][nf][1] + by);
            float2 v1 = make_float2(acc[mf][nf][2] + bx, acc[mf][nf][3] + by);
            *(float2*)(C + (size_t)r0 * N + c) = v0;
            *(float2*)(C + (size_t)r1 * N + c) = v1;
        }
    }
}

// ---------------------------------------------------------------------------
// RoPE v2: read fp32 qkv, apply rope in fp32, emit compact fp16 planes.
// q gets 0.125*log2e folded in (softmax runs in exp2 domain).
// Plane layout: [b][h][t][d] contiguous 64-half rows.
// ---------------------------------------------------------------------------
__global__ void rope2_kernel(const float* __restrict__ qkv,
                             __half* __restrict__ qh, __half* __restrict__ kh,
                             __half* __restrict__ vh) {
    int idx = blockIdx.x * blockDim.x + threadIdx.x;
    const int total = BT_ * H_ * (DH_ / 2);
    if (idx >= total) return;
    int i = idx & 31;          // pair 0..31
    int h = (idx >> 5) & 15;
    int bt = idx >> 9;         // 0..4095
    int b = bt >> 11;
    int t = bt & (T_ - 1);

    float freq = __powf(10000.f, (2.f * (float)i) / (float)DH_);
    float ang = (float)t / freq;
    float c, s;
    __sincosf(ang, &s, &c);

    const float* base = qkv + (size_t)bt * QKV_COLS + h * (3 * DH_);
    const float QSC = 0.125f * 1.44269504f;

    size_t po = (((size_t)(b * H_ + h)) * T_ + t) * DH_ + 2 * i;

    float e = base[2 * i], o = base[2 * i + 1];
    __half2 qv;
    qv.x = __float2half((e * c - o * (1.f - c)) * QSC);
    qv.y = __float2half((o * s + e * (1.f - s)) * QSC);
    *(__half2*)(qh + po) = qv;

    e = base[DH_ + 2 * i];
    o = base[DH_ + 2 * i + 1];
    __half2 kv;
    kv.x = __float2half(e * c - o * (1.f - c));
    kv.y = __float2half(o * s + e * (1.f - s));
    *(__half2*)(kh + po) = kv;

    __half2 vv;
    vv.x = __float2half(base[2 * DH_ + 2 * i]);
    vv.y = __float2half(base[2 * DH_ + 2 * i + 1]);
    *(__half2*)(vh + po) = vv;
}

// ---------------------------------------------------------------------------
// Flash attention, fp16 mma (m16n8k16). Block = (b,h, 128-query tile),
// 256 threads (8 warps x 16 rows). Bc=64, double-buffered cp.async K/V.
// S-accum layout == fp16 A-frag layout -> P needs only cvt, no shuffles.
// ---------------------------------------------------------------------------
#define HST 72   // half-stride per row (64 + 8 pad) -> 144B rows

__global__ __launch_bounds__(256, 2)
void attn_f16_kernel(const __half* __restrict__ qh, const __half* __restrict__ kh,
                     const __half* __restrict__ vh, float* __restrict__ y) {
    int bh = blockIdx.y;
    int b = bh >> 4, h = bh & 15;
    int it = gridDim.x - 1 - blockIdx.x;   // heaviest tiles first
    int m0 = it * 128;
    int tid = threadIdx.x, lane = tid & 31, wid = tid >> 5;
    int g = lane >> 2, t = lane & 3;

    extern __shared__ __half hsm[];
    __half* Qs = hsm;                    // [128][HST]
    __half* Ks = hsm + 128 * HST;        // [2][64][HST]
    __half* Vs = Ks + 2 * 64 * HST;      // [2][64][HST]
    uint32_t qsB = (uint32_t)__cvta_generic_to_shared(Qs);
    uint32_t ksB = (uint32_t)__cvta_generic_to_shared(Ks);
    uint32_t vsB = (uint32_t)__cvta_generic_to_shared(Vs);

    int lr = lane & 7, sel = lane >> 3;
    // A-frag ldsm: m0=(r0-7,k0-7) m1=(r8-15,k0-7) m2=(r0-7,k8-15) m3=(r8-15,k8-15)
    int aRow = lr + (sel & 1) * 8, aColH = (sel >> 1) * 8;
    // K B-frag ldsm: m0=(n0-7,k0-7) m1=(n0-7,k8-15) m2=(n8-15,k0-7) m3=(n8-15,k8-15)
    int bRow = lr + (sel >> 1) * 8, bColH = (sel & 1) * 8;
    // V B-frag ldsm.trans: m0=(s0-7,d0-7) m1=(s8-15,d0-7) m2=(s0-7,d8-15) m3=(s8-15,d8-15)
    int vRow = lr + (sel & 1) * 8, vColH = (sel >> 1) * 8;

    size_t plane = (((size_t)(b * H_ + h)) * T_) * DH_;
    const __half* qg = qh + plane;
    const __half* kg = kh + plane;
    const __half* vg = vh + plane;

    // stage Q tile (128 rows x 128B) + KV tile 0
    {
        for (int p = 0; p < 4; p++) {
            int j = tid + p * 256;
            int row = j >> 3, c8 = (j & 7) * 8;
            cpa16(Qs + row * HST + c8, qg + (size_t)(m0 + row) * DH_ + c8);
        }
    }
    auto loadTile = [&](int buf, int s0) {
#pragma unroll
        for (int p = 0; p < 2; p++) {
            int j = tid + p * 256;
            int row = j >> 3, c8 = (j & 7) * 8;
            cpa16(Ks + buf * 64 * HST + row * HST + c8, kg + (size_t)(s0 + row) * DH_ + c8);
            cpa16(Vs + buf * 64 * HST + row * HST + c8, vg + (size_t)(s0 + row) * DH_ + c8);
        }
    };
    loadTile(0, 0);
    CP_COMMIT();
    CP_WAIT(0);
    __syncthreads();

    // Q fragments: rows wid*16 + {g,g+8}, 4 k-steps of 16
    uint32_t qf[4][4];
#pragma unroll
    for (int kf = 0; kf < 4; kf++)
        ldsm_x4(qsB + ((wid * 16 + aRow) * HST + kf * 16 + aColH) * 2u, qf[kf]);

    float o[8][4];
#pragma unroll
    for (int nf = 0; nf < 8; nf++)
#pragma unroll
        for (int e = 0; e < 4; e++) o[nf][e] = 0.f;
    float mA = -1e30f, mB = -1e30f, lA = 0.f, lB = 0.f;

    const int nTiles = 2 * it + 2;
    const int rowMin = m0 + wid * 16;

    for (int ti = 0; ti < nTiles; ti++) {
        int s0 = ti * 64;
        if (ti > 0) { CP_WAIT(0); __syncthreads(); }
        if (ti + 1 < nTiles) { loadTile((ti + 1) & 1, s0 + 64); CP_COMMIT(); }

        if (s0 <= rowMin + 15) {
            uint32_t kB = ksB + (uint32_t)((ti & 1) * 64 * HST) * 2u;
            uint32_t vB = vsB + (uint32_t)((ti & 1) * 64 * HST) * 2u;

            // S = Qs @ Ks^T   (16x64 per warp, k=64)
            float s[8][4];
#pragma unroll
            for (int nf = 0; nf < 8; nf++)
#pragma unroll
                for (int e = 0; e < 4; e++) s[nf][e] = 0.f;
#pragma unroll
            for (int kf = 0; kf < 4; kf++) {
#pragma unroll
                for (int nfp = 0; nfp < 4; nfp++) {
                    uint32_t r4[4];
                    ldsm_x4(kB + ((nfp * 16 + bRow) * HST + kf * 16 + bColH) * 2u, r4);
                    uint32_t bf0[2] = { r4[0], r4[1] };
                    uint32_t bf1[2] = { r4[2], r4[3] };
                    mma_f16(s[2 * nfp], qf[kf], bf0);
                    mma_f16(s[2 * nfp + 1], qf[kf], bf1);
                }
            }

            // causal mask (diagonal tiles only); scale already folded into q
            if (s0 + 63 > rowMin) {
                int ra = rowMin + g, rb = ra + 8;
#pragma unroll
                for (int nf = 0; nf < 8; nf++) {
                    int c0 = s0 + nf * 8 + 2 * t, c1 = c0 + 1;
                    if (c0 > ra) s[nf][0] = -1e30f;
                    if (c1 > ra) s[nf][1] = -1e30f;
                    if (c0 > rb) s[nf][2] = -1e30f;
                    if (c1 > rb) s[nf][3] = -1e30f;
                }
            }

            // online softmax in exp2 domain
            float mtA = -1e30f, mtB = -1e30f;
#pragma unroll
            for (int nf = 0; nf < 8; nf++) {
                mtA = fmaxf(mtA, fmaxf(s[nf][0], s[nf][1]));
                mtB = fmaxf(mtB, fmaxf(s[nf][2], s[nf][3]));
            }
            mtA = fmaxf(mtA, __shfl_xor_sync(0xffffffffu, mtA, 1));
            mtA = fmaxf(mtA, __shfl_xor_sync(0xffffffffu, mtA, 2));
            mtB = fmaxf(mtB, __shfl_xor_sync(0xffffffffu, mtB, 1));
            mtB = fmaxf(mtB, __shfl_xor_sync(0xffffffffu, mtB, 2));
            float mnA = fmaxf(mA, mtA), mnB = fmaxf(mB, mtB);
            float aAl = ex2f(mA - mnA), aBl = ex2f(mB - mnB);
            float sA = 0.f, sB = 0.f;
            uint32_t pf[4][4];   // P as fp16 A-frags
#pragma unroll
            for (int nf = 0; nf < 8; nf++) {
                float p0 = ex2f(s[nf][0] - mnA);
                float p1 = ex2f(s[nf][1] - mnA);
                float p2 = ex2f(s[nf][2] - mnB);
                float p3 = ex2f(s[nf][3] - mnB);
                sA += p0 + p1;
                sB += p2 + p3;
                __half2 hA = __floats2half2_rn(p0, p1);
                __half2 hB = __floats2half2_rn(p2, p3);
                pf[nf >> 1][(nf & 1) * 2]     = *(uint32_t*)&hA;
                pf[nf >> 1][(nf & 1) * 2 + 1] = *(uint32_t*)&hB;
            }
            sA += __shfl_xor_sync(0xffffffffu, sA, 1);
            sA += __shfl_xor_sync(0xffffffffu, sA, 2);
            sB += __shfl_xor_sync(0xffffffffu, sB, 1);
            sB += __shfl_xor_sync(0xffffffffu, sB, 2);
            lA = lA * aAl + sA;
            lB = lB * aBl + sB;
            mA = mnA; mB = mnB;
#pragma unroll
            for (int nf = 0; nf < 8; nf++) {
                o[nf][0] *= aAl; o[nf][1] *= aAl;
                o[nf][2] *= aBl; o[nf][3] *= aBl;
            }

            // O += P @ V   (k = s-dim 64, 4 k-steps)
#pragma unroll
            for (int kf = 0; kf < 4; kf++) {
#pragma unroll
                for (int nfp = 0; nfp < 4; nfp++) {
                    uint32_t r4[4];
                    ldsm_x4t(vB + ((kf * 16 + vRow) * HST + nfp * 16 + vColH) * 2u, r4);
                    uint32_t bf0[2] = { r4[0], r4[1] };
                    uint32_t bf1[2] = { r4[2], r4[3] };
                    mma_f16(o[2 * nfp], pf[kf], bf0);
                    mma_f16(o[2 * nfp + 1], pf[kf], bf1);
                }
            }
        }
    }

    // epilogue: normalize, tf32-round (feeds proj GEMM), store
    float iA = 1.f / lA, iB = 1.f / lB;
    int rA = m0 + wid * 16 + g;
    float* y0 = y + (size_t)(b * T_ + rA) * D_ + h * DH_;
    float* y1 = y + (size_t)(b * T_ + rA + 8) * D_ + h * DH_;
#pragma unroll
    for (int nf = 0; nf < 8; nf++) {
        int c = nf * 8 + 2 * t;
        y0[c]     = tf32r(o[nf][0] * iA);
        y0[c + 1] = tf32r(o[nf][1] * iA);
        y1[c]     = tf32r(o[nf][2] * iB);
        y1[c + 1] = tf32r(o[nf][3] * iB);
    }
}

// ---------------------------------------------------------------------------
// Launch
// ---------------------------------------------------------------------------
extern "C" void kernel_launch(void* const* d_in, const int* in_sizes, int n_in,
                              void* d_out, int out_size) {
    const float* x     = (const float*)d_in[0];
    const float* Wqkv  = (const float*)d_in[1];
    const float* bqkv  = (const float*)d_in[2];
    const float* Wproj = (const float*)d_in[3];
    const float* bproj = (const float*)d_in[4];
    float* out = (float*)d_out;

    float *qkv, *y, *xr, *wqkvr, *wprojr;
    __half *qh, *kh, *vh;
    cudaGetSymbolAddress((void**)&qkv, g_qkv);
    cudaGetSymbolAddress((void**)&y, g_y);
    cudaGetSymbolAddress((void**)&xr, g_xr);
    cudaGetSymbolAddress((void**)&wqkvr, g_wqkvr);
    cudaGetSymbolAddress((void**)&wprojr, g_wprojr);
    cudaGetSymbolAddress((void**)&qh, g_qh);
    cudaGetSymbolAddress((void**)&kh, g_kh);
    cudaGetSymbolAddress((void**)&vh, g_vh);

    // 0) tf32-round GEMM operands
    {
        int n1 = BT_ * D_;
        round_tf32_kernel<<<(n1 + 255) / 256, 256>>>(x, xr, n1);
        int n2 = QKV_COLS * D_;
        round_tf32_kernel<<<(n2 + 255) / 256, 256>>>(Wqkv, wqkvr, n2);
        int n3 = D_ * D_;
        round_tf32_kernel<<<(n3 + 255) / 256, 256>>>(Wproj, wprojr, n3);
    }

    int gemm_smem = 3 * STG * (int)sizeof(float); // 110592 B
    cudaFuncSetAttribute(mma_gemm_v2,
                         cudaFuncAttributeMaxDynamicSharedMemorySize, gemm_smem);

    // 1) QKV GEMM (tf32)
    {
        dim3 grid(QKV_COLS / 128, BT_ / 128);
        mma_gemm_v2<<<grid, 128, gemm_smem>>>(xr, wqkvr, bqkv, qkv,
                                              BT_, QKV_COLS, D_);
    }

    // 2) RoPE -> compact fp16 planes
    {
        int total = BT_ * H_ * (DH_ / 2);
        rope2_kernel<<<(total + 255) / 256, 256>>>(qkv, qh, kh, vh);
    }

    // 3) Flash attention (fp16 mma)
    {
        int smem = (128 * HST + 4 * 64 * HST) * (int)sizeof(__half); // 55296 B
        cudaFuncSetAttribute(attn_f16_kernel,
                             cudaFuncAttributeMaxDynamicSharedMemorySize, smem);
        dim3 grid(T_ / 128, B_ * H_);
        attn_f16_kernel<<<grid, 256, smem>>>(qh, kh, vh, y);
    }

    // 4) Proj GEMM (tf32)
    {
        dim3 grid(D_ / 128, BT_ / 128);
        mma_gemm_v2<<<grid, 128, gemm_smem>>>(y, wprojr, bproj, out,
                                              BT_, D_, D_);
    }
}

// round 7
// speedup vs baseline: 8.4235x; 1.5610x over previous
#include <cuda_runtime.h>
#include <cuda_fp16.h>
#include <math.h>
#include <stdint.h>

#define B_  2
#define T_  2048
#define D_  1024
#define H_  16
#define DH_ 64
#define QKV_COLS 3072   // 3*D
#define BT_ (B_*T_)     // 4096

// Scratch (allocation-free rule: __device__ globals)
__device__ float  g_qkv[(size_t)BT_ * QKV_COLS];     // 48 MB fp32
__device__ __half g_xh[(size_t)BT_ * D_];            // 8 MB
__device__ __half g_wqkvh[(size_t)QKV_COLS * D_];    // 6 MB
__device__ __half g_wprojh[(size_t)D_ * D_];         // 2 MB
__device__ __half g_yh[(size_t)BT_ * D_];            // 8 MB
__device__ __half g_qh[(size_t)B_ * H_ * T_ * DH_];  // 8 MB (scaled *0.125*log2e)
__device__ __half g_kh[(size_t)B_ * H_ * T_ * DH_];  // 8 MB
__device__ __half g_vh[(size_t)B_ * H_ * T_ * DH_];  // 8 MB

// ---------------------------------------------------------------------------
// Helpers
// ---------------------------------------------------------------------------
__device__ __forceinline__ float ex2f(float x) {
    float r;
    asm("ex2.approx.f32 %0, %1;" : "=f"(r) : "f"(x));
    return r;
}
__device__ __forceinline__ void mma_f16(float* c, const uint32_t* a, const uint32_t* b) {
    asm volatile(
        "mma.sync.aligned.m16n8k16.row.col.f32.f16.f16.f32 "
        "{%0,%1,%2,%3}, {%4,%5,%6,%7}, {%8,%9}, {%0,%1,%2,%3};"
        : "+f"(c[0]), "+f"(c[1]), "+f"(c[2]), "+f"(c[3])
        : "r"(a[0]), "r"(a[1]), "r"(a[2]), "r"(a[3]), "r"(b[0]), "r"(b[1]));
}
__device__ __forceinline__ void ldsm_x4(uint32_t addr, uint32_t* r) {
    asm volatile("ldmatrix.sync.aligned.m8n8.x4.shared.b16 {%0,%1,%2,%3}, [%4];"
                 : "=r"(r[0]), "=r"(r[1]), "=r"(r[2]), "=r"(r[3]) : "r"(addr));
}
__device__ __forceinline__ void ldsm_x4t(uint32_t addr, uint32_t* r) {
    asm volatile("ldmatrix.sync.aligned.m8n8.x4.trans.shared.b16 {%0,%1,%2,%3}, [%4];"
                 : "=r"(r[0]), "=r"(r[1]), "=r"(r[2]), "=r"(r[3]) : "r"(addr));
}
__device__ __forceinline__ void cpa16(void* smem, const void* g) {
    uint32_t s = (uint32_t)__cvta_generic_to_shared(smem);
    asm volatile("cp.async.cg.shared.global [%0], [%1], 16;" :: "r"(s), "l"(g));
}
#define CP_COMMIT() asm volatile("cp.async.commit_group;")
#define CP_WAIT(n)  asm volatile("cp.async.wait_group %0;" :: "n"(n))

// ---------------------------------------------------------------------------
// fp16 rounding pre-pass (float2 -> half2)
// ---------------------------------------------------------------------------
__global__ void round_f16_kernel(const float* __restrict__ in,
                                 __half* __restrict__ out, int n2) {
    int i = blockIdx.x * blockDim.x + threadIdx.x;
    if (i >= n2) return;
    float2 v = ((const float2*)in)[i];
    ((__half2*)out)[i] = __floats2half2_rn(v.x, v.y);
}

// ---------------------------------------------------------------------------
// fp16 tensor-core GEMM (NT): C[m][n] = sum_k A[m][k]*W[n][k] + bias[n]
// 4 warps (2x2), warp tile 64x64, CTA tile 128x128, BK=32 halves,
// 3-stage cp.async ring, ldmatrix fragment loads, m16n8k16 mma.
// ---------------------------------------------------------------------------
#define GSH 40                 // smem row stride in halves (32 + 8 pad)
#define STGH (2*128*GSH)       // halves per stage (A tile + B tile)

__global__ __launch_bounds__(128, 2)
void gemm_f16(const __half* __restrict__ A, const __half* __restrict__ W,
              const float* __restrict__ bias, float* __restrict__ C,
              int M, int N, int K) {
    extern __shared__ __half hsm[];

    int tid = threadIdx.x, lane = tid & 31, wid = tid >> 5;
    int g = lane >> 2, t = lane & 3;
    int wm = wid >> 1, wn = wid & 1;   // 2 x 2 warp grid
    int m0 = blockIdx.y * 128, n0 = blockIdx.x * 128;

    int lr = lane & 7, sel = lane >> 3;
    int aRow = lr + (sel & 1) * 8, aColH = (sel >> 1) * 8;
    int bRow = lr + (sel >> 1) * 8, bColH = (sel & 1) * 8;

    uint32_t smBase = (uint32_t)__cvta_generic_to_shared(hsm);

    float acc[4][8][4];
#pragma unroll
    for (int i = 0; i < 4; i++)
#pragma unroll
        for (int j = 0; j < 8; j++)
#pragma unroll
            for (int e = 0; e < 4; e++) acc[i][j][e] = 0.f;

    const int nk = K / 32;

    // stage loader: A 128x32 halves + B 128x32 halves, 4 chunks/thread/operand
    auto loadStage = [&](int st, int kt) {
        __half* as = hsm + st * STGH;
        __half* bs = as + 128 * GSH;
        int k0 = kt * 32;
#pragma unroll
        for (int p = 0; p < 4; p++) {
            int idx = tid + p * 128;
            int row = idx >> 2, c8 = (idx & 3) * 8;
            cpa16(as + row * GSH + c8, A + (size_t)(m0 + row) * K + k0 + c8);
            cpa16(bs + row * GSH + c8, W + (size_t)(n0 + row) * K + k0 + c8);
        }
        CP_COMMIT();
    };

    loadStage(0, 0);
    loadStage(1, 1);

    for (int kt = 0; kt < nk; kt++) {
        if (kt + 2 < nk) { CP_WAIT(1); } else { CP_WAIT(0); }
        __syncthreads();
        if (kt + 2 < nk) loadStage((kt + 2) % 3, kt + 2);

        int st = kt % 3;
        uint32_t aB = smBase + (uint32_t)(st * STGH) * 2u;
        uint32_t bB = aB + (uint32_t)(128 * GSH) * 2u;
#pragma unroll
        for (int kk = 0; kk < 2; kk++) {       // 2 k-steps of 16
            uint32_t af[4][4], bf[8][2];
#pragma unroll
            for (int mf = 0; mf < 4; mf++)
                ldsm_x4(aB + ((wm * 64 + mf * 16 + aRow) * GSH + kk * 16 + aColH) * 2u, af[mf]);
#pragma unroll
            for (int nfp = 0; nfp < 4; nfp++) {
                uint32_t r4[4];
                ldsm_x4(bB + ((wn * 64 + nfp * 16 + bRow) * GSH + kk * 16 + bColH) * 2u, r4);
                bf[2 * nfp][0] = r4[0]; bf[2 * nfp][1] = r4[1];
                bf[2 * nfp + 1][0] = r4[2]; bf[2 * nfp + 1][1] = r4[3];
            }
#pragma unroll
            for (int mf = 0; mf < 4; mf++)
#pragma unroll
                for (int nf = 0; nf < 8; nf++)
                    mma_f16(acc[mf][nf], af[mf], bf[nf]);
        }
    }

    // epilogue (fp32 out + bias)
#pragma unroll
    for (int mf = 0; mf < 4; mf++) {
        int r0 = m0 + wm * 64 + mf * 16 + g;
        int r1 = r0 + 8;
#pragma unroll
        for (int nf = 0; nf < 8; nf++) {
            int c = n0 + wn * 64 + nf * 8 + 2 * t;
            float bx = bias[c], by = bias[c + 1];
            float2 v0 = make_float2(acc[mf][nf][0] + bx, acc[mf][nf][1] + by);
            float2 v1 = make_float2(acc[mf][nf][2] + bx, acc[mf][nf][3] + by);
            *(float2*)(C + (size_t)r0 * N + c) = v0;
            *(float2*)(C + (size_t)r1 * N + c) = v1;
        }
    }
}

// ---------------------------------------------------------------------------
// RoPE v2: read fp32 qkv, apply rope, emit compact fp16 planes.
// q gets 0.125*log2e folded in. Plane layout: [b][h][t][d].
// ---------------------------------------------------------------------------
__global__ void rope2_kernel(const float* __restrict__ qkv,
                             __half* __restrict__ qh, __half* __restrict__ kh,
                             __half* __restrict__ vh) {
    int idx = blockIdx.x * blockDim.x + threadIdx.x;
    const int total = BT_ * H_ * (DH_ / 2);
    if (idx >= total) return;
    int i = idx & 31;
    int h = (idx >> 5) & 15;
    int bt = idx >> 9;
    int b = bt >> 11;
    int t = bt & (T_ - 1);

    float freq = __powf(10000.f, (2.f * (float)i) / (float)DH_);
    float ang = (float)t / freq;
    float c, s;
    __sincosf(ang, &s, &c);

    const float* base = qkv + (size_t)bt * QKV_COLS + h * (3 * DH_);
    const float QSC = 0.125f * 1.44269504f;

    size_t po = (((size_t)(b * H_ + h)) * T_ + t) * DH_ + 2 * i;

    float e = base[2 * i], o = base[2 * i + 1];
    *(__half2*)(qh + po) = __floats2half2_rn((e * c - o * (1.f - c)) * QSC,
                                             (o * s + e * (1.f - s)) * QSC);
    e = base[DH_ + 2 * i];
    o = base[DH_ + 2 * i + 1];
    *(__half2*)(kh + po) = __floats2half2_rn(e * c - o * (1.f - c),
                                             o * s + e * (1.f - s));
    *(__half2*)(vh + po) = __floats2half2_rn(base[2 * DH_ + 2 * i],
                                             base[2 * DH_ + 2 * i + 1]);
}

// ---------------------------------------------------------------------------
// Flash attention, fp16 mma (m16n8k16). Unchanged from R6 except the
// epilogue writes fp16 y directly (feeds the fp16 proj GEMM).
// ---------------------------------------------------------------------------
#define HST 72   // half-stride per row (64 + 8 pad)

__global__ __launch_bounds__(256, 2)
void attn_f16_kernel(const __half* __restrict__ qh, const __half* __restrict__ kh,
                     const __half* __restrict__ vh, __half* __restrict__ yh) {
    int bh = blockIdx.y;
    int b = bh >> 4, h = bh & 15;
    int it = gridDim.x - 1 - blockIdx.x;
    int m0 = it * 128;
    int tid = threadIdx.x, lane = tid & 31, wid = tid >> 5;
    int g = lane >> 2, t = lane & 3;

    extern __shared__ __half hsm[];
    __half* Qs = hsm;                    // [128][HST]
    __half* Ks = hsm + 128 * HST;        // [2][64][HST]
    __half* Vs = Ks + 2 * 64 * HST;      // [2][64][HST]
    uint32_t qsB = (uint32_t)__cvta_generic_to_shared(Qs);
    uint32_t ksB = (uint32_t)__cvta_generic_to_shared(Ks);
    uint32_t vsB = (uint32_t)__cvta_generic_to_shared(Vs);

    int lr = lane & 7, sel = lane >> 3;
    int aRow = lr + (sel & 1) * 8, aColH = (sel >> 1) * 8;
    int bRow = lr + (sel >> 1) * 8, bColH = (sel & 1) * 8;
    int vRow = lr + (sel & 1) * 8, vColH = (sel >> 1) * 8;

    size_t plane = (((size_t)(b * H_ + h)) * T_) * DH_;
    const __half* qg = qh + plane;
    const __half* kg = kh + plane;
    const __half* vg = vh + plane;

    for (int p = 0; p < 4; p++) {
        int j = tid + p * 256;
        int row = j >> 3, c8 = (j & 7) * 8;
        cpa16(Qs + row * HST + c8, qg + (size_t)(m0 + row) * DH_ + c8);
    }
    auto loadTile = [&](int buf, int s0) {
#pragma unroll
        for (int p = 0; p < 2; p++) {
            int j = tid + p * 256;
            int row = j >> 3, c8 = (j & 7) * 8;
            cpa16(Ks + buf * 64 * HST + row * HST + c8, kg + (size_t)(s0 + row) * DH_ + c8);
            cpa16(Vs + buf * 64 * HST + row * HST + c8, vg + (size_t)(s0 + row) * DH_ + c8);
        }
    };
    loadTile(0, 0);
    CP_COMMIT();
    CP_WAIT(0);
    __syncthreads();

    uint32_t qf[4][4];
#pragma unroll
    for (int kf = 0; kf < 4; kf++)
        ldsm_x4(qsB + ((wid * 16 + aRow) * HST + kf * 16 + aColH) * 2u, qf[kf]);

    float o[8][4];
#pragma unroll
    for (int nf = 0; nf < 8; nf++)
#pragma unroll
        for (int e = 0; e < 4; e++) o[nf][e] = 0.f;
    float mA = -1e30f, mB = -1e30f, lA = 0.f, lB = 0.f;

    const int nTiles = 2 * it + 2;
    const int rowMin = m0 + wid * 16;

    for (int ti = 0; ti < nTiles; ti++) {
        int s0 = ti * 64;
        if (ti > 0) { CP_WAIT(0); __syncthreads(); }
        if (ti + 1 < nTiles) { loadTile((ti + 1) & 1, s0 + 64); CP_COMMIT(); }

        if (s0 <= rowMin + 15) {
            uint32_t kB = ksB + (uint32_t)((ti & 1) * 64 * HST) * 2u;
            uint32_t vB = vsB + (uint32_t)((ti & 1) * 64 * HST) * 2u;

            float s[8][4];
#pragma unroll
            for (int nf = 0; nf < 8; nf++)
#pragma unroll
                for (int e = 0; e < 4; e++) s[nf][e] = 0.f;
#pragma unroll
            for (int kf = 0; kf < 4; kf++) {
#pragma unroll
                for (int nfp = 0; nfp < 4; nfp++) {
                    uint32_t r4[4];
                    ldsm_x4(kB + ((nfp * 16 + bRow) * HST + kf * 16 + bColH) * 2u, r4);
                    uint32_t bf0[2] = { r4[0], r4[1] };
                    uint32_t bf1[2] = { r4[2], r4[3] };
                    mma_f16(s[2 * nfp], qf[kf], bf0);
                    mma_f16(s[2 * nfp + 1], qf[kf], bf1);
                }
            }

            if (s0 + 63 > rowMin) {
                int ra = rowMin + g, rb = ra + 8;
#pragma unroll
                for (int nf = 0; nf < 8; nf++) {
                    int c0 = s0 + nf * 8 + 2 * t, c1 = c0 + 1;
                    if (c0 > ra) s[nf][0] = -1e30f;
                    if (c1 > ra) s[nf][1] = -1e30f;
                    if (c0 > rb) s[nf][2] = -1e30f;
                    if (c1 > rb) s[nf][3] = -1e30f;
                }
            }

            float mtA = -1e30f, mtB = -1e30f;
#pragma unroll
            for (int nf = 0; nf < 8; nf++) {
                mtA = fmaxf(mtA, fmaxf(s[nf][0], s[nf][1]));
                mtB = fmaxf(mtB, fmaxf(s[nf][2], s[nf][3]));
            }
            mtA = fmaxf(mtA, __shfl_xor_sync(0xffffffffu, mtA, 1));
            mtA = fmaxf(mtA, __shfl_xor_sync(0xffffffffu, mtA, 2));
            mtB = fmaxf(mtB, __shfl_xor_sync(0xffffffffu, mtB, 1));
            mtB = fmaxf(mtB, __shfl_xor_sync(0xffffffffu, mtB, 2));
            float mnA = fmaxf(mA, mtA), mnB = fmaxf(mB, mtB);
            float aAl = ex2f(mA - mnA), aBl = ex2f(mB - mnB);
            float sA = 0.f, sB = 0.f;
            uint32_t pf[4][4];
#pragma unroll
            for (int nf = 0; nf < 8; nf++) {
                float p0 = ex2f(s[nf][0] - mnA);
                float p1 = ex2f(s[nf][1] - mnA);
                float p2 = ex2f(s[nf][2] - mnB);
                float p3 = ex2f(s[nf][3] - mnB);
                sA += p0 + p1;
                sB += p2 + p3;
                __half2 hA = __floats2half2_rn(p0, p1);
                __half2 hB = __floats2half2_rn(p2, p3);
                pf[nf >> 1][(nf & 1) * 2]     = *(uint32_t*)&hA;
                pf[nf >> 1][(nf & 1) * 2 + 1] = *(uint32_t*)&hB;
            }
            sA += __shfl_xor_sync(0xffffffffu, sA, 1);
            sA += __shfl_xor_sync(0xffffffffu, sA, 2);
            sB += __shfl_xor_sync(0xffffffffu, sB, 1);
            sB += __shfl_xor_sync(0xffffffffu, sB, 2);
            lA = lA * aAl + sA;
            lB = lB * aBl + sB;
            mA = mnA; mB = mnB;
#pragma unroll
            for (int nf = 0; nf < 8; nf++) {
                o[nf][0] *= aAl; o[nf][1] *= aAl;
                o[nf][2] *= aBl; o[nf][3] *= aBl;
            }

#pragma unroll
            for (int kf = 0; kf < 4; kf++) {
#pragma unroll
                for (int nfp = 0; nfp < 4; nfp++) {
                    uint32_t r4[4];
                    ldsm_x4t(vB + ((kf * 16 + vRow) * HST + nfp * 16 + vColH) * 2u, r4);
                    uint32_t bf0[2] = { r4[0], r4[1] };
                    uint32_t bf1[2] = { r4[2], r4[3] };
                    mma_f16(o[2 * nfp], pf[kf], bf0);
                    mma_f16(o[2 * nfp + 1], pf[kf], bf1);
                }
            }
        }
    }

    // epilogue: normalize, write fp16 y (feeds fp16 proj GEMM)
    float iA = 1.f / lA, iB = 1.f / lB;
    int rA = m0 + wid * 16 + g;
    __half* y0 = yh + (size_t)(b * T_ + rA) * D_ + h * DH_;
    __half* y1 = yh + (size_t)(b * T_ + rA + 8) * D_ + h * DH_;
#pragma unroll
    for (int nf = 0; nf < 8; nf++) {
        int c = nf * 8 + 2 * t;
        *(__half2*)(y0 + c) = __floats2half2_rn(o[nf][0] * iA, o[nf][1] * iA);
        *(__half2*)(y1 + c) = __floats2half2_rn(o[nf][2] * iB, o[nf][3] * iB);
    }
}

// ---------------------------------------------------------------------------
// Launch
// ---------------------------------------------------------------------------
extern "C" void kernel_launch(void* const* d_in, const int* in_sizes, int n_in,
                              void* d_out, int out_size) {
    const float* x     = (const float*)d_in[0];
    const float* Wqkv  = (const float*)d_in[1];
    const float* bqkv  = (const float*)d_in[2];
    const float* Wproj = (const float*)d_in[3];
    const float* bproj = (const float*)d_in[4];
    float* out = (float*)d_out;

    float* qkv;
    __half *xh, *wqkvh, *wprojh, *yh, *qh, *kh, *vh;
    cudaGetSymbolAddress((void**)&qkv, g_qkv);
    cudaGetSymbolAddress((void**)&xh, g_xh);
    cudaGetSymbolAddress((void**)&wqkvh, g_wqkvh);
    cudaGetSymbolAddress((void**)&wprojh, g_wprojh);
    cudaGetSymbolAddress((void**)&yh, g_yh);
    cudaGetSymbolAddress((void**)&qh, g_qh);
    cudaGetSymbolAddress((void**)&kh, g_kh);
    cudaGetSymbolAddress((void**)&vh, g_vh);

    // 0) fp16 rounding of GEMM operands
    {
        int n1 = BT_ * D_ / 2;
        round_f16_kernel<<<(n1 + 255) / 256, 256>>>(x, xh, n1);
        int n2 = QKV_COLS * D_ / 2;
        round_f16_kernel<<<(n2 + 255) / 256, 256>>>(Wqkv, wqkvh, n2);
        int n3 = D_ * D_ / 2;
        round_f16_kernel<<<(n3 + 255) / 256, 256>>>(Wproj, wprojh, n3);
    }

    int gemm_smem = 3 * STGH * (int)sizeof(__half); // 61440 B
    cudaFuncSetAttribute(gemm_f16,
                         cudaFuncAttributeMaxDynamicSharedMemorySize, gemm_smem);

    // 1) QKV GEMM (fp16 mma)
    {
        dim3 grid(QKV_COLS / 128, BT_ / 128);
        gemm_f16<<<grid, 128, gemm_smem>>>(xh, wqkvh, bqkv, qkv,
                                           BT_, QKV_COLS, D_);
    }

    // 2) RoPE -> compact fp16 planes
    {
        int total = BT_ * H_ * (DH_ / 2);
        rope2_kernel<<<(total + 255) / 256, 256>>>(qkv, qh, kh, vh);
    }

    // 3) Flash attention (fp16 mma), writes fp16 y
    {
        int smem = (128 * HST + 4 * 64 * HST) * (int)sizeof(__half); // 55296 B
        cudaFuncSetAttribute(attn_f16_kernel,
                             cudaFuncAttributeMaxDynamicSharedMemorySize, smem);
        dim3 grid(T_ / 128, B_ * H_);
        attn_f16_kernel<<<grid, 256, smem>>>(qh, kh, vh, yh);
    }

    // 4) Proj GEMM (fp16 mma)
    {
        dim3 grid(D_ / 128, BT_ / 128);
        gemm_f16<<<grid, 128, gemm_smem>>>(yh, wprojh, bproj, out,
                                           BT_, D_, D_);
    }
}

// round 8
// speedup vs baseline: 8.4399x; 1.0019x over previous
#include <cuda_runtime.h>
#include <cuda_fp16.h>
#include <math.h>
#include <stdint.h>

#define B_  2
#define T_  2048
#define D_  1024
#define H_  16
#define DH_ 64
#define QKV_COLS 3072   // 3*D
#define BT_ (B_*T_)     // 4096

// Scratch (allocation-free rule: __device__ globals)
__device__ __half g_xh[(size_t)BT_ * D_];            // 8 MB
__device__ __half g_wqkvh[(size_t)QKV_COLS * D_];    // 6 MB
__device__ __half g_wprojh[(size_t)D_ * D_];         // 2 MB
__device__ __half g_yh[(size_t)BT_ * D_];            // 8 MB
__device__ __half g_qh[(size_t)B_ * H_ * T_ * DH_];  // 8 MB (scaled *0.125*log2e)
__device__ __half g_kh[(size_t)B_ * H_ * T_ * DH_];  // 8 MB
__device__ __half g_vh[(size_t)B_ * H_ * T_ * DH_];  // 8 MB

// ---------------------------------------------------------------------------
// Helpers
// ---------------------------------------------------------------------------
__device__ __forceinline__ float ex2f(float x) {
    float r;
    asm("ex2.approx.f32 %0, %1;" : "=f"(r) : "f"(x));
    return r;
}
__device__ __forceinline__ void mma_f16(float* c, const uint32_t* a, const uint32_t* b) {
    asm volatile(
        "mma.sync.aligned.m16n8k16.row.col.f32.f16.f16.f32 "
        "{%0,%1,%2,%3}, {%4,%5,%6,%7}, {%8,%9}, {%0,%1,%2,%3};"
        : "+f"(c[0]), "+f"(c[1]), "+f"(c[2]), "+f"(c[3])
        : "r"(a[0]), "r"(a[1]), "r"(a[2]), "r"(a[3]), "r"(b[0]), "r"(b[1]));
}
__device__ __forceinline__ void ldsm_x4(uint32_t addr, uint32_t* r) {
    asm volatile("ldmatrix.sync.aligned.m8n8.x4.shared.b16 {%0,%1,%2,%3}, [%4];"
                 : "=r"(r[0]), "=r"(r[1]), "=r"(r[2]), "=r"(r[3]) : "r"(addr));
}
__device__ __forceinline__ void ldsm_x4t(uint32_t addr, uint32_t* r) {
    asm volatile("ldmatrix.sync.aligned.m8n8.x4.trans.shared.b16 {%0,%1,%2,%3}, [%4];"
                 : "=r"(r[0]), "=r"(r[1]), "=r"(r[2]), "=r"(r[3]) : "r"(addr));
}
__device__ __forceinline__ void cpa16(void* smem, const void* g) {
    uint32_t s = (uint32_t)__cvta_generic_to_shared(smem);
    asm volatile("cp.async.cg.shared.global [%0], [%1], 16;" :: "r"(s), "l"(g));
}
#define CP_COMMIT() asm volatile("cp.async.commit_group;")
#define CP_WAIT(n)  asm volatile("cp.async.wait_group %0;" :: "n"(n))

// ---------------------------------------------------------------------------
// fp16 rounding pre-pass (float2 -> half2)
// ---------------------------------------------------------------------------
__global__ void round_f16_kernel(const float* __restrict__ in,
                                 __half* __restrict__ out, int n2) {
    int i = blockIdx.x * blockDim.x + threadIdx.x;
    if (i >= n2) return;
    float2 v = ((const float2*)in)[i];
    ((__half2*)out)[i] = __floats2half2_rn(v.x, v.y);
}

// ---------------------------------------------------------------------------
// fp16 tensor-core GEMM (NT): 4 warps (2x2), warp tile 64x64, CTA 128x128,
// BK=32 halves, 4-stage cp.async ring, ldmatrix frags, m16n8k16 mma.
// EPI=0: C[m][n] = acc + bias[n] (fp32)
// EPI=1: fused rope epilogue -> writes q/k/v fp16 planes [b][h][t][d]
// ---------------------------------------------------------------------------
#define GSH 40                 // smem row stride in halves (32 + 8 pad)
#define STGH (2*128*GSH)       // halves per stage (A tile + B tile)
#define NSTG 4

template <int EPI>
__global__ __launch_bounds__(128, 2)
void gemm_f16(const __half* __restrict__ A, const __half* __restrict__ W,
              const float* __restrict__ bias, float* __restrict__ C,
              __half* __restrict__ qh, __half* __restrict__ kh,
              __half* __restrict__ vh, int M, int N, int K) {
    extern __shared__ __half hsm[];

    int tid = threadIdx.x, lane = tid & 31, wid = tid >> 5;
    int g = lane >> 2, t = lane & 3;
    int wm = wid >> 1, wn = wid & 1;
    int m0 = blockIdx.y * 128, n0 = blockIdx.x * 128;

    int lr = lane & 7, sel = lane >> 3;
    int aRow = lr + (sel & 1) * 8, aColH = (sel >> 1) * 8;
    int bRow = lr + (sel >> 1) * 8, bColH = (sel & 1) * 8;

    uint32_t smBase = (uint32_t)__cvta_generic_to_shared(hsm);

    float acc[4][8][4];
#pragma unroll
    for (int i = 0; i < 4; i++)
#pragma unroll
        for (int j = 0; j < 8; j++)
#pragma unroll
            for (int e = 0; e < 4; e++) acc[i][j][e] = 0.f;

    const int nk = K / 32;

    auto loadStage = [&](int st, int kt) {
        __half* as = hsm + st * STGH;
        __half* bs = as + 128 * GSH;
        int k0 = kt * 32;
#pragma unroll
        for (int p = 0; p < 4; p++) {
            int idx = tid + p * 128;
            int row = idx >> 2, c8 = (idx & 3) * 8;
            cpa16(as + row * GSH + c8, A + (size_t)(m0 + row) * K + k0 + c8);
            cpa16(bs + row * GSH + c8, W + (size_t)(n0 + row) * K + k0 + c8);
        }
        CP_COMMIT();
    };

    loadStage(0, 0);
    loadStage(1, 1);
    loadStage(2, 2);

    for (int kt = 0; kt < nk; kt++) {
        int rem = nk - kt;
        if (rem > 2) { CP_WAIT(2); } else if (rem == 2) { CP_WAIT(1); } else { CP_WAIT(0); }
        __syncthreads();
        if (kt + 3 < nk) loadStage((kt + 3) & (NSTG - 1), kt + 3);

        int st = kt & (NSTG - 1);
        uint32_t aB = smBase + (uint32_t)(st * STGH) * 2u;
        uint32_t bB = aB + (uint32_t)(128 * GSH) * 2u;
#pragma unroll
        for (int kk = 0; kk < 2; kk++) {
            uint32_t af[4][4], bf[8][2];
#pragma unroll
            for (int mf = 0; mf < 4; mf++)
                ldsm_x4(aB + ((wm * 64 + mf * 16 + aRow) * GSH + kk * 16 + aColH) * 2u, af[mf]);
#pragma unroll
            for (int nfp = 0; nfp < 4; nfp++) {
                uint32_t r4[4];
                ldsm_x4(bB + ((wn * 64 + nfp * 16 + bRow) * GSH + kk * 16 + bColH) * 2u, r4);
                bf[2 * nfp][0] = r4[0]; bf[2 * nfp][1] = r4[1];
                bf[2 * nfp + 1][0] = r4[2]; bf[2 * nfp + 1][1] = r4[3];
            }
#pragma unroll
            for (int mf = 0; mf < 4; mf++)
#pragma unroll
                for (int nf = 0; nf < 8; nf++)
                    mma_f16(acc[mf][nf], af[mf], bf[nf]);
        }
    }

    if (EPI == 0) {
        // plain epilogue: fp32 out + bias
#pragma unroll
        for (int mf = 0; mf < 4; mf++) {
            int r0 = m0 + wm * 64 + mf * 16 + g;
            int r1 = r0 + 8;
#pragma unroll
            for (int nf = 0; nf < 8; nf++) {
                int c = n0 + wn * 64 + nf * 8 + 2 * t;
                float bx = bias[c], by = bias[c + 1];
                float2 v0 = make_float2(acc[mf][nf][0] + bx, acc[mf][nf][1] + by);
                float2 v1 = make_float2(acc[mf][nf][2] + bx, acc[mf][nf][3] + by);
                *(float2*)(C + (size_t)r0 * N + c) = v0;
                *(float2*)(C + (size_t)r1 * N + c) = v1;
            }
        }
    } else {
        // fused rope epilogue: bias -> rope -> fp16 planes
        const float QSC = 0.125f * 1.44269504f;
        const float L2_10K = 13.2877123795f;   // log2(10000)
        // per-nf column metadata
        int nn[8], hh[8], dd[8], sub[8];
        float invf[8], bx[8], by[8];
#pragma unroll
        for (int nf = 0; nf < 8; nf++) {
            int n = n0 + wn * 64 + nf * 8 + 2 * t;
            nn[nf] = n;
            int h = n / 192;
            int r = n - h * 192;
            hh[nf] = h;
            sub[nf] = r >> 6;
            int d = r & 63;
            dd[nf] = d;
            invf[nf] = ex2f(-((float)(d & ~1) / 64.f) * L2_10K);  // 10000^{-2i/64}
            bx[nf] = bias[n];
            by[nf] = bias[n + 1];
        }
#pragma unroll
        for (int mf = 0; mf < 4; mf++) {
#pragma unroll
            for (int hr = 0; hr < 2; hr++) {
                int row = m0 + wm * 64 + mf * 16 + g + hr * 8;
                int b = row >> 11;
                int tpos = row & (T_ - 1);
                float ftp = (float)tpos;
#pragma unroll
                for (int nf = 0; nf < 8; nf++) {
                    float e = acc[mf][nf][hr * 2]     + bx[nf];
                    float o = acc[mf][nf][hr * 2 + 1] + by[nf];
                    size_t po = (((size_t)(b * H_ + hh[nf])) * T_ + tpos) * DH_ + dd[nf];
                    if (sub[nf] == 2) {
                        *(__half2*)(vh + po) = __floats2half2_rn(e, o);
                    } else {
                        float sn, cs;
                        __sincosf(ftp * invf[nf], &sn, &cs);
                        float re = e * cs - o * (1.f - cs);
                        float ro = o * sn + e * (1.f - sn);
                        if (sub[nf] == 0) {
                            *(__half2*)(qh + po) = __floats2half2_rn(re * QSC, ro * QSC);
                        } else {
                            *(__half2*)(kh + po) = __floats2half2_rn(re, ro);
                        }
                    }
                }
            }
        }
    }
}

// ---------------------------------------------------------------------------
// Flash attention, fp16 mma (m16n8k16) — unchanged from R7.
// ---------------------------------------------------------------------------
#define HST 72   // half-stride per row (64 + 8 pad)

__global__ __launch_bounds__(256, 2)
void attn_f16_kernel(const __half* __restrict__ qh, const __half* __restrict__ kh,
                     const __half* __restrict__ vh, __half* __restrict__ yh) {
    int bh = blockIdx.y;
    int b = bh >> 4, h = bh & 15;
    int it = gridDim.x - 1 - blockIdx.x;
    int m0 = it * 128;
    int tid = threadIdx.x, lane = tid & 31, wid = tid >> 5;
    int g = lane >> 2, t = lane & 3;

    extern __shared__ __half hsm[];
    __half* Qs = hsm;
    __half* Ks = hsm + 128 * HST;
    __half* Vs = Ks + 2 * 64 * HST;
    uint32_t qsB = (uint32_t)__cvta_generic_to_shared(Qs);
    uint32_t ksB = (uint32_t)__cvta_generic_to_shared(Ks);
    uint32_t vsB = (uint32_t)__cvta_generic_to_shared(Vs);

    int lr = lane & 7, sel = lane >> 3;
    int aRow = lr + (sel & 1) * 8, aColH = (sel >> 1) * 8;
    int bRow = lr + (sel >> 1) * 8, bColH = (sel & 1) * 8;
    int vRow = lr + (sel & 1) * 8, vColH = (sel >> 1) * 8;

    size_t plane = (((size_t)(b * H_ + h)) * T_) * DH_;
    const __half* qg = qh + plane;
    const __half* kg = kh + plane;
    const __half* vg = vh + plane;

    for (int p = 0; p < 4; p++) {
        int j = tid + p * 256;
        int row = j >> 3, c8 = (j & 7) * 8;
        cpa16(Qs + row * HST + c8, qg + (size_t)(m0 + row) * DH_ + c8);
    }
    auto loadTile = [&](int buf, int s0) {
#pragma unroll
        for (int p = 0; p < 2; p++) {
            int j = tid + p * 256;
            int row = j >> 3, c8 = (j & 7) * 8;
            cpa16(Ks + buf * 64 * HST + row * HST + c8, kg + (size_t)(s0 + row) * DH_ + c8);
            cpa16(Vs + buf * 64 * HST + row * HST + c8, vg + (size_t)(s0 + row) * DH_ + c8);
        }
    };
    loadTile(0, 0);
    CP_COMMIT();
    CP_WAIT(0);
    __syncthreads();

    uint32_t qf[4][4];
#pragma unroll
    for (int kf = 0; kf < 4; kf++)
        ldsm_x4(qsB + ((wid * 16 + aRow) * HST + kf * 16 + aColH) * 2u, qf[kf]);

    float o[8][4];
#pragma unroll
    for (int nf = 0; nf < 8; nf++)
#pragma unroll
        for (int e = 0; e < 4; e++) o[nf][e] = 0.f;
    float mA = -1e30f, mB = -1e30f, lA = 0.f, lB = 0.f;

    const int nTiles = 2 * it + 2;
    const int rowMin = m0 + wid * 16;

    for (int ti = 0; ti < nTiles; ti++) {
        int s0 = ti * 64;
        if (ti > 0) { CP_WAIT(0); __syncthreads(); }
        if (ti + 1 < nTiles) { loadTile((ti + 1) & 1, s0 + 64); CP_COMMIT(); }

        if (s0 <= rowMin + 15) {
            uint32_t kB = ksB + (uint32_t)((ti & 1) * 64 * HST) * 2u;
            uint32_t vB = vsB + (uint32_t)((ti & 1) * 64 * HST) * 2u;

            float s[8][4];
#pragma unroll
            for (int nf = 0; nf < 8; nf++)
#pragma unroll
                for (int e = 0; e < 4; e++) s[nf][e] = 0.f;
#pragma unroll
            for (int kf = 0; kf < 4; kf++) {
#pragma unroll
                for (int nfp = 0; nfp < 4; nfp++) {
                    uint32_t r4[4];
                    ldsm_x4(kB + ((nfp * 16 + bRow) * HST + kf * 16 + bColH) * 2u, r4);
                    uint32_t bf0[2] = { r4[0], r4[1] };
                    uint32_t bf1[2] = { r4[2], r4[3] };
                    mma_f16(s[2 * nfp], qf[kf], bf0);
                    mma_f16(s[2 * nfp + 1], qf[kf], bf1);
                }
            }

            if (s0 + 63 > rowMin) {
                int ra = rowMin + g, rb = ra + 8;
#pragma unroll
                for (int nf = 0; nf < 8; nf++) {
                    int c0 = s0 + nf * 8 + 2 * t, c1 = c0 + 1;
                    if (c0 > ra) s[nf][0] = -1e30f;
                    if (c1 > ra) s[nf][1] = -1e30f;
                    if (c0 > rb) s[nf][2] = -1e30f;
                    if (c1 > rb) s[nf][3] = -1e30f;
                }
            }

            float mtA = -1e30f, mtB = -1e30f;
#pragma unroll
            for (int nf = 0; nf < 8; nf++) {
                mtA = fmaxf(mtA, fmaxf(s[nf][0], s[nf][1]));
                mtB = fmaxf(mtB, fmaxf(s[nf][2], s[nf][3]));
            }
            mtA = fmaxf(mtA, __shfl_xor_sync(0xffffffffu, mtA, 1));
            mtA = fmaxf(mtA, __shfl_xor_sync(0xffffffffu, mtA, 2));
            mtB = fmaxf(mtB, __shfl_xor_sync(0xffffffffu, mtB, 1));
            mtB = fmaxf(mtB, __shfl_xor_sync(0xffffffffu, mtB, 2));
            float mnA = fmaxf(mA, mtA), mnB = fmaxf(mB, mtB);
            float aAl = ex2f(mA - mnA), aBl = ex2f(mB - mnB);
            float sA = 0.f, sB = 0.f;
            uint32_t pf[4][4];
#pragma unroll
            for (int nf = 0; nf < 8; nf++) {
                float p0 = ex2f(s[nf][0] - mnA);
                float p1 = ex2f(s[nf][1] - mnA);
                float p2 = ex2f(s[nf][2] - mnB);
                float p3 = ex2f(s[nf][3] - mnB);
                sA += p0 + p1;
                sB += p2 + p3;
                __half2 hA = __floats2half2_rn(p0, p1);
                __half2 hB = __floats2half2_rn(p2, p3);
                pf[nf >> 1][(nf & 1) * 2]     = *(uint32_t*)&hA;
                pf[nf >> 1][(nf & 1) * 2 + 1] = *(uint32_t*)&hB;
            }
            sA += __shfl_xor_sync(0xffffffffu, sA, 1);
            sA += __shfl_xor_sync(0xffffffffu, sA, 2);
            sB += __shfl_xor_sync(0xffffffffu, sB, 1);
            sB += __shfl_xor_sync(0xffffffffu, sB, 2);
            lA = lA * aAl + sA;
            lB = lB * aBl + sB;
            mA = mnA; mB = mnB;
#pragma unroll
            for (int nf = 0; nf < 8; nf++) {
                o[nf][0] *= aAl; o[nf][1] *= aAl;
                o[nf][2] *= aBl; o[nf][3] *= aBl;
            }

#pragma unroll
            for (int kf = 0; kf < 4; kf++) {
#pragma unroll
                for (int nfp = 0; nfp < 4; nfp++) {
                    uint32_t r4[4];
                    ldsm_x4t(vB + ((kf * 16 + vRow) * HST + nfp * 16 + vColH) * 2u, r4);
                    uint32_t bf0[2] = { r4[0], r4[1] };
                    uint32_t bf1[2] = { r4[2], r4[3] };
                    mma_f16(o[2 * nfp], pf[kf], bf0);
                    mma_f16(o[2 * nfp + 1], pf[kf], bf1);
                }
            }
        }
    }

    float iA = 1.f / lA, iB = 1.f / lB;
    int rA = m0 + wid * 16 + g;
    __half* y0 = yh + (size_t)(b * T_ + rA) * D_ + h * DH_;
    __half* y1 = yh + (size_t)(b * T_ + rA + 8) * D_ + h * DH_;
#pragma unroll
    for (int nf = 0; nf < 8; nf++) {
        int c = nf * 8 + 2 * t;
        *(__half2*)(y0 + c) = __floats2half2_rn(o[nf][0] * iA, o[nf][1] * iA);
        *(__half2*)(y1 + c) = __floats2half2_rn(o[nf][2] * iB, o[nf][3] * iB);
    }
}

// ---------------------------------------------------------------------------
// Launch
// ---------------------------------------------------------------------------
extern "C" void kernel_launch(void* const* d_in, const int* in_sizes, int n_in,
                              void* d_out, int out_size) {
    const float* x     = (const float*)d_in[0];
    const float* Wqkv  = (const float*)d_in[1];
    const float* bqkv  = (const float*)d_in[2];
    const float* Wproj = (const float*)d_in[3];
    const float* bproj = (const float*)d_in[4];
    float* out = (float*)d_out;

    __half *xh, *wqkvh, *wprojh, *yh, *qh, *kh, *vh;
    cudaGetSymbolAddress((void**)&xh, g_xh);
    cudaGetSymbolAddress((void**)&wqkvh, g_wqkvh);
    cudaGetSymbolAddress((void**)&wprojh, g_wprojh);
    cudaGetSymbolAddress((void**)&yh, g_yh);
    cudaGetSymbolAddress((void**)&qh, g_qh);
    cudaGetSymbolAddress((void**)&kh, g_kh);
    cudaGetSymbolAddress((void**)&vh, g_vh);

    // 0) fp16 rounding of GEMM operands
    {
        int n1 = BT_ * D_ / 2;
        round_f16_kernel<<<(n1 + 255) / 256, 256>>>(x, xh, n1);
        int n2 = QKV_COLS * D_ / 2;
        round_f16_kernel<<<(n2 + 255) / 256, 256>>>(Wqkv, wqkvh, n2);
        int n3 = D_ * D_ / 2;
        round_f16_kernel<<<(n3 + 255) / 256, 256>>>(Wproj, wprojh, n3);
    }

    int gemm_smem = NSTG * STGH * (int)sizeof(__half); // 81920 B
    cudaFuncSetAttribute(gemm_f16<0>,
                         cudaFuncAttributeMaxDynamicSharedMemorySize, gemm_smem);
    cudaFuncSetAttribute(gemm_f16<1>,
                         cudaFuncAttributeMaxDynamicSharedMemorySize, gemm_smem);

    // 1) QKV GEMM + fused rope -> fp16 q/k/v planes
    {
        dim3 grid(QKV_COLS / 128, BT_ / 128);
        gemm_f16<1><<<grid, 128, gemm_smem>>>(xh, wqkvh, bqkv, nullptr,
                                              qh, kh, vh, BT_, QKV_COLS, D_);
    }

    // 2) Flash attention (fp16 mma), writes fp16 y
    {
        int smem = (128 * HST + 4 * 64 * HST) * (int)sizeof(__half); // 55296 B
        cudaFuncSetAttribute(attn_f16_kernel,
                             cudaFuncAttributeMaxDynamicSharedMemorySize, smem);
        dim3 grid(T_ / 128, B_ * H_);
        attn_f16_kernel<<<grid, 256, smem>>>(qh, kh, vh, yh);
    }

    // 3) Proj GEMM (fp16 mma) -> fp32 out
    {
        dim3 grid(D_ / 128, BT_ / 128);
        gemm_f16<0><<<grid, 128, gemm_smem>>>(yh, wprojh, bproj, out,
                                              nullptr, nullptr, nullptr,
                                              BT_, D_, D_);
    }
}

// round 9
// speedup vs baseline: 8.8298x; 1.0462x over previous
#include <cuda_runtime.h>
#include <cuda_fp16.h>
#include <math.h>
#include <stdint.h>

#define B_  2
#define T_  2048
#define D_  1024
#define H_  16
#define DH_ 64
#define QKV_COLS 3072   // 3*D
#define BT_ (B_*T_)     // 4096

// Scratch (allocation-free rule: __device__ globals)
__device__ __half g_xh[(size_t)BT_ * D_];            // 8 MB
__device__ __half g_wqkvh[(size_t)QKV_COLS * D_];    // 6 MB
__device__ __half g_wprojh[(size_t)D_ * D_];         // 2 MB
__device__ __half g_yh[(size_t)BT_ * D_];            // 8 MB
__device__ __half g_qh[(size_t)B_ * H_ * T_ * DH_];  // 8 MB (scaled *0.125*log2e)
__device__ __half g_kh[(size_t)B_ * H_ * T_ * DH_];  // 8 MB
__device__ __half g_vh[(size_t)B_ * H_ * T_ * DH_];  // 8 MB

// ---------------------------------------------------------------------------
// Helpers
// ---------------------------------------------------------------------------
__device__ __forceinline__ float ex2f(float x) {
    float r;
    asm("ex2.approx.f32 %0, %1;" : "=f"(r) : "f"(x));
    return r;
}
__device__ __forceinline__ uint32_t h2ex2(uint32_t x) {
    uint32_t r;
    asm("ex2.approx.f16x2 %0, %1;" : "=r"(r) : "r"(x));
    return r;
}
__device__ __forceinline__ void mma_f16(float* c, const uint32_t* a, const uint32_t* b) {
    asm volatile(
        "mma.sync.aligned.m16n8k16.row.col.f32.f16.f16.f32 "
        "{%0,%1,%2,%3}, {%4,%5,%6,%7}, {%8,%9}, {%0,%1,%2,%3};"
        : "+f"(c[0]), "+f"(c[1]), "+f"(c[2]), "+f"(c[3])
        : "r"(a[0]), "r"(a[1]), "r"(a[2]), "r"(a[3]), "r"(b[0]), "r"(b[1]));
}
__device__ __forceinline__ void ldsm_x4(uint32_t addr, uint32_t* r) {
    asm volatile("ldmatrix.sync.aligned.m8n8.x4.shared.b16 {%0,%1,%2,%3}, [%4];"
                 : "=r"(r[0]), "=r"(r[1]), "=r"(r[2]), "=r"(r[3]) : "r"(addr));
}
__device__ __forceinline__ void ldsm_x4t(uint32_t addr, uint32_t* r) {
    asm volatile("ldmatrix.sync.aligned.m8n8.x4.trans.shared.b16 {%0,%1,%2,%3}, [%4];"
                 : "=r"(r[0]), "=r"(r[1]), "=r"(r[2]), "=r"(r[3]) : "r"(addr));
}
__device__ __forceinline__ void cpa16(void* smem, const void* g) {
    uint32_t s = (uint32_t)__cvta_generic_to_shared(smem);
    asm volatile("cp.async.cg.shared.global [%0], [%1], 16;" :: "r"(s), "l"(g));
}
#define CP_COMMIT() asm volatile("cp.async.commit_group;")
#define CP_WAIT(n)  asm volatile("cp.async.wait_group %0;" :: "n"(n))

// ---------------------------------------------------------------------------
// Merged fp16 rounding pre-pass (x, Wqkv, Wproj in one launch)
// ---------------------------------------------------------------------------
#define N1H (BT_*D_/2)
#define N2H (QKV_COLS*D_/2)
#define N3H (D_*D_/2)
__global__ void round3_kernel(const float* __restrict__ x, __half* __restrict__ xh,
                              const float* __restrict__ wq, __half* __restrict__ wqh,
                              const float* __restrict__ wp, __half* __restrict__ wph) {
    int i = blockIdx.x * blockDim.x + threadIdx.x;
    if (i < N1H) {
        float2 v = ((const float2*)x)[i];
        ((__half2*)xh)[i] = __floats2half2_rn(v.x, v.y);
    } else if (i < N1H + N2H) {
        int j = i - N1H;
        float2 v = ((const float2*)wq)[j];
        ((__half2*)wqh)[j] = __floats2half2_rn(v.x, v.y);
    } else if (i < N1H + N2H + N3H) {
        int j = i - N1H - N2H;
        float2 v = ((const float2*)wp)[j];
        ((__half2*)wph)[j] = __floats2half2_rn(v.x, v.y);
    }
}

// ---------------------------------------------------------------------------
// fp16 tensor-core GEMM (NT): 4 warps (2x2), warp tile 64x64, CTA 128x128,
// BK=32 halves, 4-stage cp.async ring, ldmatrix frags, m16n8k16 mma.
// EPI=0: C[m][n] = acc + bias[n] (fp32)
// EPI=1: fused rope epilogue -> writes q/k/v fp16 planes [b][h][t][d]
// ---------------------------------------------------------------------------
#define GSH 40                 // smem row stride in halves (32 + 8 pad)
#define STGH (2*128*GSH)       // halves per stage (A tile + B tile)
#define NSTG 4

template <int EPI>
__global__ __launch_bounds__(128, 2)
void gemm_f16(const __half* __restrict__ A, const __half* __restrict__ W,
              const float* __restrict__ bias, float* __restrict__ C,
              __half* __restrict__ qh, __half* __restrict__ kh,
              __half* __restrict__ vh, int M, int N, int K) {
    extern __shared__ __half hsm[];

    int tid = threadIdx.x, lane = tid & 31, wid = tid >> 5;
    int g = lane >> 2, t = lane & 3;
    int wm = wid >> 1, wn = wid & 1;
    int m0 = blockIdx.y * 128, n0 = blockIdx.x * 128;

    int lr = lane & 7, sel = lane >> 3;
    int aRow = lr + (sel & 1) * 8, aColH = (sel >> 1) * 8;
    int bRow = lr + (sel >> 1) * 8, bColH = (sel & 1) * 8;

    uint32_t smBase = (uint32_t)__cvta_generic_to_shared(hsm);

    float acc[4][8][4];
#pragma unroll
    for (int i = 0; i < 4; i++)
#pragma unroll
        for (int j = 0; j < 8; j++)
#pragma unroll
            for (int e = 0; e < 4; e++) acc[i][j][e] = 0.f;

    const int nk = K / 32;

    auto loadStage = [&](int st, int kt) {
        __half* as = hsm + st * STGH;
        __half* bs = as + 128 * GSH;
        int k0 = kt * 32;
#pragma unroll
        for (int p = 0; p < 4; p++) {
            int idx = tid + p * 128;
            int row = idx >> 2, c8 = (idx & 3) * 8;
            cpa16(as + row * GSH + c8, A + (size_t)(m0 + row) * K + k0 + c8);
            cpa16(bs + row * GSH + c8, W + (size_t)(n0 + row) * K + k0 + c8);
        }
        CP_COMMIT();
    };

    loadStage(0, 0);
    loadStage(1, 1);
    loadStage(2, 2);

    for (int kt = 0; kt < nk; kt++) {
        int rem = nk - kt;
        if (rem > 2) { CP_WAIT(2); } else if (rem == 2) { CP_WAIT(1); } else { CP_WAIT(0); }
        __syncthreads();
        if (kt + 3 < nk) loadStage((kt + 3) & (NSTG - 1), kt + 3);

        int st = kt & (NSTG - 1);
        uint32_t aB = smBase + (uint32_t)(st * STGH) * 2u;
        uint32_t bB = aB + (uint32_t)(128 * GSH) * 2u;
#pragma unroll
        for (int kk = 0; kk < 2; kk++) {
            uint32_t af[4][4], bf[8][2];
#pragma unroll
            for (int mf = 0; mf < 4; mf++)
                ldsm_x4(aB + ((wm * 64 + mf * 16 + aRow) * GSH + kk * 16 + aColH) * 2u, af[mf]);
#pragma unroll
            for (int nfp = 0; nfp < 4; nfp++) {
                uint32_t r4[4];
                ldsm_x4(bB + ((wn * 64 + nfp * 16 + bRow) * GSH + kk * 16 + bColH) * 2u, r4);
                bf[2 * nfp][0] = r4[0]; bf[2 * nfp][1] = r4[1];
                bf[2 * nfp + 1][0] = r4[2]; bf[2 * nfp + 1][1] = r4[3];
            }
#pragma unroll
            for (int mf = 0; mf < 4; mf++)
#pragma unroll
                for (int nf = 0; nf < 8; nf++)
                    mma_f16(acc[mf][nf], af[mf], bf[nf]);
        }
    }

    if (EPI == 0) {
#pragma unroll
        for (int mf = 0; mf < 4; mf++) {
            int r0 = m0 + wm * 64 + mf * 16 + g;
            int r1 = r0 + 8;
#pragma unroll
            for (int nf = 0; nf < 8; nf++) {
                int c = n0 + wn * 64 + nf * 8 + 2 * t;
                float bx = bias[c], by = bias[c + 1];
                float2 v0 = make_float2(acc[mf][nf][0] + bx, acc[mf][nf][1] + by);
                float2 v1 = make_float2(acc[mf][nf][2] + bx, acc[mf][nf][3] + by);
                *(float2*)(C + (size_t)r0 * N + c) = v0;
                *(float2*)(C + (size_t)r1 * N + c) = v1;
            }
        }
    } else {
        const float QSC = 0.125f * 1.44269504f;
        const float L2_10K = 13.2877123795f;
        int hh[8], dd[8], sub[8];
        float invf[8], bx[8], by[8];
#pragma unroll
        for (int nf = 0; nf < 8; nf++) {
            int n = n0 + wn * 64 + nf * 8 + 2 * t;
            int h = n / 192;
            int r = n - h * 192;
            hh[nf] = h;
            sub[nf] = r >> 6;
            int d = r & 63;
            dd[nf] = d;
            invf[nf] = ex2f(-((float)(d & ~1) / 64.f) * L2_10K);
            bx[nf] = bias[n];
            by[nf] = bias[n + 1];
        }
#pragma unroll
        for (int mf = 0; mf < 4; mf++) {
#pragma unroll
            for (int hr = 0; hr < 2; hr++) {
                int row = m0 + wm * 64 + mf * 16 + g + hr * 8;
                int b = row >> 11;
                int tpos = row & (T_ - 1);
                float ftp = (float)tpos;
#pragma unroll
                for (int nf = 0; nf < 8; nf++) {
                    float e = acc[mf][nf][hr * 2]     + bx[nf];
                    float o = acc[mf][nf][hr * 2 + 1] + by[nf];
                    size_t po = (((size_t)(b * H_ + hh[nf])) * T_ + tpos) * DH_ + dd[nf];
                    if (sub[nf] == 2) {
                        *(__half2*)(vh + po) = __floats2half2_rn(e, o);
                    } else {
                        float sn, cs;
                        __sincosf(ftp * invf[nf], &sn, &cs);
                        float re = e * cs - o * (1.f - cs);
                        float ro = o * sn + e * (1.f - sn);
                        if (sub[nf] == 0) {
                            *(__half2*)(qh + po) = __floats2half2_rn(re * QSC, ro * QSC);
                        } else {
                            *(__half2*)(kh + po) = __floats2half2_rn(re, ro);
                        }
                    }
                }
            }
        }
    }
}

// ---------------------------------------------------------------------------
// Flash attention, fp16 mma. New in R9:
//   - l accumulated via ones-MMA (exact row-sums of the fp16 P used by PV)
//   - ex2.approx.f16x2 softmax exponent (2 values / MUFU op)
//   - warp-vote rescale skip when no row max changed
// ---------------------------------------------------------------------------
#define HST 72   // half-stride per row (64 + 8 pad)

__global__ __launch_bounds__(256, 2)
void attn_f16_kernel(const __half* __restrict__ qh, const __half* __restrict__ kh,
                     const __half* __restrict__ vh, __half* __restrict__ yh) {
    int bh = blockIdx.y;
    int b = bh >> 4, h = bh & 15;
    int it = gridDim.x - 1 - blockIdx.x;
    int m0 = it * 128;
    int tid = threadIdx.x, lane = tid & 31, wid = tid >> 5;
    int g = lane >> 2, t = lane & 3;

    extern __shared__ __half hsm[];
    __half* Qs = hsm;
    __half* Ks = hsm + 128 * HST;
    __half* Vs = Ks + 2 * 64 * HST;
    uint32_t qsB = (uint32_t)__cvta_generic_to_shared(Qs);
    uint32_t ksB = (uint32_t)__cvta_generic_to_shared(Ks);
    uint32_t vsB = (uint32_t)__cvta_generic_to_shared(Vs);

    int lr = lane & 7, sel = lane >> 3;
    int aRow = lr + (sel & 1) * 8, aColH = (sel >> 1) * 8;
    int bRow = lr + (sel >> 1) * 8, bColH = (sel & 1) * 8;
    int vRow = lr + (sel & 1) * 8, vColH = (sel >> 1) * 8;

    size_t plane = (((size_t)(b * H_ + h)) * T_) * DH_;
    const __half* qg = qh + plane;
    const __half* kg = kh + plane;
    const __half* vg = vh + plane;

    for (int p = 0; p < 4; p++) {
        int j = tid + p * 256;
        int row = j >> 3, c8 = (j & 7) * 8;
        cpa16(Qs + row * HST + c8, qg + (size_t)(m0 + row) * DH_ + c8);
    }
    auto loadTile = [&](int buf, int s0) {
#pragma unroll
        for (int p = 0; p < 2; p++) {
            int j = tid + p * 256;
            int row = j >> 3, c8 = (j & 7) * 8;
            cpa16(Ks + buf * 64 * HST + row * HST + c8, kg + (size_t)(s0 + row) * DH_ + c8);
            cpa16(Vs + buf * 64 * HST + row * HST + c8, vg + (size_t)(s0 + row) * DH_ + c8);
        }
    };
    loadTile(0, 0);
    CP_COMMIT();
    CP_WAIT(0);
    __syncthreads();

    uint32_t qf[4][4];
#pragma unroll
    for (int kf = 0; kf < 4; kf++)
        ldsm_x4(qsB + ((wid * 16 + aRow) * HST + kf * 16 + aColH) * 2u, qf[kf]);

    float o[8][4];
#pragma unroll
    for (int nf = 0; nf < 8; nf++)
#pragma unroll
        for (int e = 0; e < 4; e++) o[nf][e] = 0.f;
    float lacc[4] = {0.f, 0.f, 0.f, 0.f};   // rows g / g+8 sums via ones-MMA
    float mA = -1e30f, mB = -1e30f;

    const uint32_t one2 = 0x3C003C00u;      // (1.0h, 1.0h)
    uint32_t bones[2] = { one2, one2 };

    const int nTiles = 2 * it + 2;
    const int rowMin = m0 + wid * 16;

    for (int ti = 0; ti < nTiles; ti++) {
        int s0 = ti * 64;
        if (ti > 0) { CP_WAIT(0); __syncthreads(); }
        if (ti + 1 < nTiles) { loadTile((ti + 1) & 1, s0 + 64); CP_COMMIT(); }

        if (s0 <= rowMin + 15) {
            uint32_t kB = ksB + (uint32_t)((ti & 1) * 64 * HST) * 2u;
            uint32_t vB = vsB + (uint32_t)((ti & 1) * 64 * HST) * 2u;

            float s[8][4];
#pragma unroll
            for (int nf = 0; nf < 8; nf++)
#pragma unroll
                for (int e = 0; e < 4; e++) s[nf][e] = 0.f;
#pragma unroll
            for (int kf = 0; kf < 4; kf++) {
#pragma unroll
                for (int nfp = 0; nfp < 4; nfp++) {
                    uint32_t r4[4];
                    ldsm_x4(kB + ((nfp * 16 + bRow) * HST + kf * 16 + bColH) * 2u, r4);
                    uint32_t bf0[2] = { r4[0], r4[1] };
                    uint32_t bf1[2] = { r4[2], r4[3] };
                    mma_f16(s[2 * nfp], qf[kf], bf0);
                    mma_f16(s[2 * nfp + 1], qf[kf], bf1);
                }
            }

            if (s0 + 63 > rowMin) {
                int ra = rowMin + g, rb = ra + 8;
#pragma unroll
                for (int nf = 0; nf < 8; nf++) {
                    int c0 = s0 + nf * 8 + 2 * t, c1 = c0 + 1;
                    if (c0 > ra) s[nf][0] = -1e30f;
                    if (c1 > ra) s[nf][1] = -1e30f;
                    if (c0 > rb) s[nf][2] = -1e30f;
                    if (c1 > rb) s[nf][3] = -1e30f;
                }
            }

            float mtA = -1e30f, mtB = -1e30f;
#pragma unroll
            for (int nf = 0; nf < 8; nf++) {
                mtA = fmaxf(mtA, fmaxf(s[nf][0], s[nf][1]));
                mtB = fmaxf(mtB, fmaxf(s[nf][2], s[nf][3]));
            }
            mtA = fmaxf(mtA, __shfl_xor_sync(0xffffffffu, mtA, 1));
            mtA = fmaxf(mtA, __shfl_xor_sync(0xffffffffu, mtA, 2));
            mtB = fmaxf(mtB, __shfl_xor_sync(0xffffffffu, mtB, 1));
            mtB = fmaxf(mtB, __shfl_xor_sync(0xffffffffu, mtB, 2));
            float mnA = fmaxf(mA, mtA), mnB = fmaxf(mB, mtB);

            bool nochg = (mnA == mA) & (mnB == mB);
            if (!__all_sync(0xffffffffu, nochg)) {
                float aAl = ex2f(mA - mnA), aBl = ex2f(mB - mnB);
#pragma unroll
                for (int nf = 0; nf < 8; nf++) {
                    o[nf][0] *= aAl; o[nf][1] *= aAl;
                    o[nf][2] *= aBl; o[nf][3] *= aBl;
                }
                lacc[0] *= aAl; lacc[1] *= aAl;
                lacc[2] *= aBl; lacc[3] *= aBl;
            }
            mA = mnA; mB = mnB;

            // P = exp2(s - m) directly in fp16 (half2 MUFU)
            uint32_t pf[4][4];
#pragma unroll
            for (int nf = 0; nf < 8; nf++) {
                __half2 dA = __floats2half2_rn(s[nf][0] - mnA, s[nf][1] - mnA);
                __half2 dB = __floats2half2_rn(s[nf][2] - mnB, s[nf][3] - mnB);
                pf[nf >> 1][(nf & 1) * 2]     = h2ex2(*(uint32_t*)&dA);
                pf[nf >> 1][(nf & 1) * 2 + 1] = h2ex2(*(uint32_t*)&dB);
            }

            // O += P @ V ;  l += P @ 1
#pragma unroll
            for (int kf = 0; kf < 4; kf++) {
                mma_f16(lacc, pf[kf], bones);
#pragma unroll
                for (int nfp = 0; nfp < 4; nfp++) {
                    uint32_t r4[4];
                    ldsm_x4t(vB + ((kf * 16 + vRow) * HST + nfp * 16 + vColH) * 2u, r4);
                    uint32_t bf0[2] = { r4[0], r4[1] };
                    uint32_t bf1[2] = { r4[2], r4[3] };
                    mma_f16(o[2 * nfp], pf[kf], bf0);
                    mma_f16(o[2 * nfp + 1], pf[kf], bf1);
                }
            }
        }
    }

    float iA = 1.f / lacc[0], iB = 1.f / lacc[2];
    int rA = m0 + wid * 16 + g;
    __half* y0 = yh + (size_t)(b * T_ + rA) * D_ + h * DH_;
    __half* y1 = yh + (size_t)(b * T_ + rA + 8) * D_ + h * DH_;
#pragma unroll
    for (int nf = 0; nf < 8; nf++) {
        int c = nf * 8 + 2 * t;
        *(__half2*)(y0 + c) = __floats2half2_rn(o[nf][0] * iA, o[nf][1] * iA);
        *(__half2*)(y1 + c) = __floats2half2_rn(o[nf][2] * iB, o[nf][3] * iB);
    }
}

// ---------------------------------------------------------------------------
// Launch
// ---------------------------------------------------------------------------
extern "C" void kernel_launch(void* const* d_in, const int* in_sizes, int n_in,
                              void* d_out, int out_size) {
    const float* x     = (const float*)d_in[0];
    const float* Wqkv  = (const float*)d_in[1];
    const float* bqkv  = (const float*)d_in[2];
    const float* Wproj = (const float*)d_in[3];
    const float* bproj = (const float*)d_in[4];
    float* out = (float*)d_out;

    __half *xh, *wqkvh, *wprojh, *yh, *qh, *kh, *vh;
    cudaGetSymbolAddress((void**)&xh, g_xh);
    cudaGetSymbolAddress((void**)&wqkvh, g_wqkvh);
    cudaGetSymbolAddress((void**)&wprojh, g_wprojh);
    cudaGetSymbolAddress((void**)&yh, g_yh);
    cudaGetSymbolAddress((void**)&qh, g_qh);
    cudaGetSymbolAddress((void**)&kh, g_kh);
    cudaGetSymbolAddress((void**)&vh, g_vh);

    // 0) single merged fp16 rounding pre-pass
    {
        int total = N1H + N2H + N3H;
        round3_kernel<<<(total + 255) / 256, 256>>>(x, xh, Wqkv, wqkvh, Wproj, wprojh);
    }

    int gemm_smem = NSTG * STGH * (int)sizeof(__half); // 81920 B
    cudaFuncSetAttribute(gemm_f16<0>,
                         cudaFuncAttributeMaxDynamicSharedMemorySize, gemm_smem);
    cudaFuncSetAttribute(gemm_f16<1>,
                         cudaFuncAttributeMaxDynamicSharedMemorySize, gemm_smem);

    // 1) QKV GEMM + fused rope -> fp16 q/k/v planes
    {
        dim3 grid(QKV_COLS / 128, BT_ / 128);
        gemm_f16<1><<<grid, 128, gemm_smem>>>(xh, wqkvh, bqkv, nullptr,
                                              qh, kh, vh, BT_, QKV_COLS, D_);
    }

    // 2) Flash attention (fp16 mma), writes fp16 y
    {
        int smem = (128 * HST + 4 * 64 * HST) * (int)sizeof(__half); // 55296 B
        cudaFuncSetAttribute(attn_f16_kernel,
                             cudaFuncAttributeMaxDynamicSharedMemorySize, smem);
        dim3 grid(T_ / 128, B_ * H_);
        attn_f16_kernel<<<grid, 256, smem>>>(qh, kh, vh, yh);
    }

    // 3) Proj GEMM (fp16 mma) -> fp32 out
    {
        dim3 grid(D_ / 128, BT_ / 128);
        gemm_f16<0><<<grid, 128, gemm_smem>>>(yh, wprojh, bproj, out,
                                              nullptr, nullptr, nullptr,
                                              BT_, D_, D_);
    }
}